// round 5
// baseline (speedup 1.0000x reference)
#include <cuda_runtime.h>
#include <mma.h>
#include <math.h>
#include <cstdint>

using namespace nvcuda;

#define HID    2304
#define HALF_D 1152
#define NHEADS 16
#define DH     144
#define SLEN   2048
#define MMAX   8192

// -------- scratch (static device globals; no runtime allocation) ----------
__device__ float g_q[(size_t)MMAX * HID];
__device__ float g_k[(size_t)MMAX * HID];
__device__ float g_v[(size_t)MMAX * HID];
__device__ float g_attn[(size_t)MMAX * HID];
__device__ float g_o[(size_t)MMAX * HID];
__device__ float g_cos[SLEN * HALF_D];
__device__ float g_sin[SLEN * HALF_D];
__device__ double g_omega[HALF_D];

// ---------------------------------------------------------------------------
// RoPE tables. Omega in double, then double angle reduction + float sincos.
// ---------------------------------------------------------------------------
__global__ void build_omega_kernel() {
    int i = blockIdx.x * blockDim.x + threadIdx.x;
    if (i < HALF_D) {
        double scale = (2.0 * (double)i) / (double)HID;
        g_omega[i] = exp(-scale * log(10000.0));
    }
}

__global__ void build_rope_kernel() {
    int idx = blockIdx.x * blockDim.x + threadIdx.x;
    if (idx >= SLEN * HALF_D) return;
    int pos = idx / HALF_D;
    int i   = idx - pos * HALF_D;
    double ang = (double)pos * g_omega[i];
    double n = floor(ang * 0.15915494309189535);
    double r = ang - n * 6.283185307179586476925286766559;
    float s, c;
    sincosf((float)r, &s, &c);
    g_cos[idx] = c;
    g_sin[idx] = s;
}

// ---------------------------------------------------------------------------
// cp.async helpers
// ---------------------------------------------------------------------------
__device__ __forceinline__ void cp_async16(uint32_t dst, const float* src) {
    asm volatile("cp.async.cg.shared.global [%0], [%1], 16;\n" :: "r"(dst), "l"(src));
}
__device__ __forceinline__ void cp_commit() {
    asm volatile("cp.async.commit_group;\n");
}
__device__ __forceinline__ void cp_wait1() {
    asm volatile("cp.async.wait_group 1;\n");
}
__device__ __forceinline__ void cp_wait0() {
    asm volatile("cp.async.wait_group 0;\n");
}

// ---------------------------------------------------------------------------
// C[M,N] = A[M,K] @ B[N,K]^T via tf32 wmma (raw f32 bits, HW truncation).
// CTA tile 128x256x32, 3-stage cp.async pipeline, 8 warps (2x4), 64x64/warp.
// Epilogue modes: 0 = direct store; 1 = +bias; 2 = +bias then RoPE.
// ---------------------------------------------------------------------------
#define BM 128
#define BN 256
#define BK 32
#define LDS_PAD 40
#define STAGE_FLOATS ((BM + BN) * LDS_PAD)        // 15360 floats
#define GEMM_SMEM_BYTES (3 * STAGE_FLOATS * 4)    // 184320 B
#define LDC 260                                   // multiple of 4 for wmma store

__device__ __forceinline__ void load_stage(const float* __restrict__ A,
                                           const float* __restrict__ B,
                                           int K, int bm, int bn, int k0,
                                           float* As, float* Bs, int tid) {
    uint32_t sA = (uint32_t)__cvta_generic_to_shared(As);
    uint32_t sB = (uint32_t)__cvta_generic_to_shared(Bs);
    #pragma unroll
    for (int i = 0; i < 4; i++) {
        int e = i * 256 + tid;
        int r = e >> 3;
        int c = (e & 7) * 4;
        cp_async16(sA + (uint32_t)(r * LDS_PAD + c) * 4,
                   A + (size_t)(bm + r) * K + k0 + c);
    }
    #pragma unroll
    for (int i = 0; i < 8; i++) {
        int e = i * 256 + tid;
        int r = e >> 3;
        int c = (e & 7) * 4;
        cp_async16(sB + (uint32_t)(r * LDS_PAD + c) * 4,
                   B + (size_t)(bn + r) * K + k0 + c);
    }
}

__global__ __launch_bounds__(256, 1)
void gemm_tf32_kernel(const float* __restrict__ A, const float* __restrict__ B,
                      float* __restrict__ C, const float* __restrict__ bias,
                      int M, int N, int K, int mode) {
    extern __shared__ float smem[];

    int bm  = blockIdx.y * BM;
    int bn  = blockIdx.x * BN;
    int tid = threadIdx.x;
    int warp = tid >> 5;
    int wm = (warp >> 2) * 64;   // 2 warps along M
    int wn = (warp & 3) * 64;    // 4 warps along N

    wmma::fragment<wmma::accumulator, 16, 16, 8, float> acc[4][4];
    #pragma unroll
    for (int i = 0; i < 4; i++)
        #pragma unroll
        for (int j = 0; j < 4; j++)
            wmma::fill_fragment(acc[i][j], 0.0f);

    int kIters = K / BK;

    load_stage(A, B, K, bm, bn, 0, smem, smem + BM * LDS_PAD, tid);
    cp_commit();
    load_stage(A, B, K, bm, bn, BK, smem + STAGE_FLOATS,
               smem + STAGE_FLOATS + BM * LDS_PAD, tid);
    cp_commit();

    int stage = 0;
    for (int kt = 0; kt < kIters; kt++) {
        cp_wait1();
        __syncthreads();

        int nk = kt + 2;
        if (nk < kIters) {
            int ns = nk % 3;
            load_stage(A, B, K, bm, bn, nk * BK,
                       smem + ns * STAGE_FLOATS,
                       smem + ns * STAGE_FLOATS + BM * LDS_PAD, tid);
        }
        cp_commit();

        const float* As = smem + stage * STAGE_FLOATS;
        const float* Bs = As + BM * LDS_PAD;

        #pragma unroll
        for (int kk = 0; kk < BK; kk += 8) {
            wmma::fragment<wmma::matrix_a, 16, 16, 8, wmma::precision::tf32, wmma::row_major> af[4];
            #pragma unroll
            for (int i = 0; i < 4; i++)
                wmma::load_matrix_sync(af[i], As + (wm + i * 16) * LDS_PAD + kk, LDS_PAD);
            #pragma unroll
            for (int j = 0; j < 4; j++) {
                wmma::fragment<wmma::matrix_b, 16, 16, 8, wmma::precision::tf32, wmma::col_major> bf;
                wmma::load_matrix_sync(bf, Bs + (wn + j * 16) * LDS_PAD + kk, LDS_PAD);
                #pragma unroll
                for (int i = 0; i < 4; i++)
                    wmma::mma_sync(acc[i][j], af[i], bf, acc[i][j]);
            }
        }

        stage = (stage + 1 == 3) ? 0 : stage + 1;
    }

    if (mode == 0) {
        // direct store
        #pragma unroll
        for (int i = 0; i < 4; i++)
            #pragma unroll
            for (int j = 0; j < 4; j++)
                wmma::store_matrix_sync(C + (size_t)(bm + wm + i * 16) * N + (bn + wn + j * 16),
                                        acc[i][j], N, wmma::mem_row_major);
        return;
    }

    // fused epilogue: stage C tile in smem (reuse pipeline buffers)
    cp_wait0();
    __syncthreads();
    #pragma unroll
    for (int i = 0; i < 4; i++)
        #pragma unroll
        for (int j = 0; j < 4; j++)
            wmma::store_matrix_sync(smem + (wm + i * 16) * LDC + wn + j * 16,
                                    acc[i][j], LDC, wmma::mem_row_major);
    __syncthreads();

    if (mode == 1) {
        // bias only (v)
        for (int e = tid; e < BM * (BN / 2); e += 256) {
            int r = e >> 7;            // 0..127
            int p = e & 127;           // pair index within tile
            int col = bn + 2 * p;
            float v0 = smem[r * LDC + 2 * p]     + bias[col];
            float v1 = smem[r * LDC + 2 * p + 1] + bias[col + 1];
            float* dst = C + (size_t)(bm + r) * N + col;
            dst[0] = v0;
            dst[1] = v1;
        }
    } else {
        // bias + RoPE (q, k)
        for (int e = tid; e < BM * (BN / 2); e += 256) {
            int r = e >> 7;
            int p = e & 127;
            int col = bn + 2 * p;
            int i = col >> 1;
            int pos = (bm + r) & (SLEN - 1);
            float c = g_cos[pos * HALF_D + i];
            float s = g_sin[pos * HALF_D + i];
            float x0 = smem[r * LDC + 2 * p]     + bias[col];
            float x1 = smem[r * LDC + 2 * p + 1] + bias[col + 1];
            float* dst = C + (size_t)(bm + r) * N + col;
            dst[0] = c * x0 - s * x1;
            dst[1] = s * x0 + c * x1;
        }
    }
}

// ======================= head-mixing attention =============================
__global__ __launch_bounds__(256)
void attention_kernel(int M) {
    __shared__ float qt[DH * NHEADS];
    __shared__ float kt[DH * NHEADS];
    __shared__ float vs[HID];
    __shared__ float w[NHEADS * NHEADS];

    int p = blockIdx.x;
    int t = threadIdx.x;
    const float* qrow = g_q + (size_t)p * HID;
    const float* krow = g_k + (size_t)p * HID;
    const float* vrow = g_v + (size_t)p * HID;

    for (int c = t; c < HID; c += 256) {
        int n = c / DH;
        int j = c - n * DH;
        qt[j * NHEADS + n] = qrow[c];
        kt[j * NHEADS + n] = krow[c];
        vs[c] = vrow[c];
    }
    __syncthreads();

    {
        int m = t >> 4;
        int n = t & 15;
        float acc = 0.0f;
        #pragma unroll 8
        for (int j = 0; j < DH; j++)
            acc += qt[j * NHEADS + n] * kt[j * NHEADS + m];
        w[n * NHEADS + m] = acc * (1.0f / 12.0f);
    }
    __syncthreads();

    if (t < NHEADS) {
        float mx = -1e30f;
        #pragma unroll
        for (int m = 0; m < NHEADS; m++) mx = fmaxf(mx, w[t * NHEADS + m]);
        float sum = 0.0f;
        #pragma unroll
        for (int m = 0; m < NHEADS; m++) {
            float e = expf(w[t * NHEADS + m] - mx);
            w[t * NHEADS + m] = e;
            sum += e;
        }
        float inv = 1.0f / sum;
        #pragma unroll
        for (int m = 0; m < NHEADS; m++) w[t * NHEADS + m] *= inv;
    }
    __syncthreads();

    float* arow = g_attn + (size_t)p * HID;
    for (int c = t; c < HID; c += 256) {
        int n = c / DH;
        int j = c - n * DH;
        float acc = 0.0f;
        #pragma unroll
        for (int m = 0; m < NHEADS; m++)
            acc += w[n * NHEADS + m] * vs[m * DH + j];
        arow[c] = acc;
    }
}

// ======================= residual + LayerNorm ==============================
__device__ __forceinline__ float block_sum(float v, float* red) {
    #pragma unroll
    for (int o = 16; o > 0; o >>= 1) v += __shfl_xor_sync(0xFFFFFFFFu, v, o);
    int warp = threadIdx.x >> 5, lane = threadIdx.x & 31;
    if (lane == 0) red[warp] = v;
    __syncthreads();
    if (warp == 0) {
        float x = (lane < 8) ? red[lane] : 0.0f;
        #pragma unroll
        for (int o = 4; o > 0; o >>= 1) x += __shfl_xor_sync(0xFFFFFFFFu, x, o);
        if (lane == 0) red[0] = x;
    }
    __syncthreads();
    float r = red[0];
    __syncthreads();
    return r;
}

__global__ __launch_bounds__(256)
void ln_kernel(const float* __restrict__ x, const float* __restrict__ bo,
               const float* __restrict__ gamma, const float* __restrict__ beta,
               float* __restrict__ out) {
    __shared__ float ybuf[HID];
    __shared__ float red[8];

    int row = blockIdx.x;
    int t = threadIdx.x;
    const float* xr = x + (size_t)row * HID;
    const float* orow = g_o + (size_t)row * HID;

    float s = 0.0f;
    for (int c = t; c < HID; c += 256) {
        float y = xr[c] + orow[c] + bo[c];
        ybuf[c] = y;
        s += y;
    }
    float total = block_sum(s, red);
    float mu = total * (1.0f / (float)HID);

    float vsum = 0.0f;
    for (int c = t; c < HID; c += 256) {
        float dy = ybuf[c] - mu;
        vsum += dy * dy;
    }
    float vtot = block_sum(vsum, red);
    float var = vtot * (1.0f / (float)HID);
    float rstd = rsqrtf(var + 1e-5f);

    float* orow_out = out + (size_t)row * HID;
    for (int c = t; c < HID; c += 256) {
        orow_out[c] = (ybuf[c] - mu) * rstd * gamma[c] + beta[c];
    }
}

// ---------------------------------------------------------------------------
extern "C" void kernel_launch(void* const* d_in, const int* in_sizes, int n_in,
                              void* d_out, int out_size) {
    const float* x  = (const float*)d_in[0];
    const float* wq = (const float*)d_in[1];
    const float* bq = (const float*)d_in[2];
    const float* wk = (const float*)d_in[3];
    const float* bk = (const float*)d_in[4];
    const float* wv = (const float*)d_in[5];
    const float* bv = (const float*)d_in[6];
    const float* wo = (const float*)d_in[7];
    const float* bo = (const float*)d_in[8];
    const float* g  = (const float*)d_in[9];
    const float* bl = (const float*)d_in[10];
    float* out = (float*)d_out;

    int M = in_sizes[0] / HID;   // b*s = 8192

    float *q, *k, *v, *attn, *o;
    cudaGetSymbolAddress((void**)&q,    g_q);
    cudaGetSymbolAddress((void**)&k,    g_k);
    cudaGetSymbolAddress((void**)&v,    g_v);
    cudaGetSymbolAddress((void**)&attn, g_attn);
    cudaGetSymbolAddress((void**)&o,    g_o);

    static int smem_set = 0;
    if (!smem_set) {
        cudaFuncSetAttribute(gemm_tf32_kernel,
                             cudaFuncAttributeMaxDynamicSharedMemorySize,
                             GEMM_SMEM_BYTES);
        smem_set = 1;
    }

    build_omega_kernel<<<(HALF_D + 255) / 256, 256>>>();
    build_rope_kernel<<<(SLEN * HALF_D + 255) / 256, 256>>>();

    dim3 ggrid(HID / BN, M / BM);   // 9 x 64
    gemm_tf32_kernel<<<ggrid, 256, GEMM_SMEM_BYTES>>>(x, wq, q, bq, M, HID, HID, 2);
    gemm_tf32_kernel<<<ggrid, 256, GEMM_SMEM_BYTES>>>(x, wk, k, bk, M, HID, HID, 2);
    gemm_tf32_kernel<<<ggrid, 256, GEMM_SMEM_BYTES>>>(x, wv, v, bv, M, HID, HID, 1);

    attention_kernel<<<M, 256>>>(M);

    gemm_tf32_kernel<<<ggrid, 256, GEMM_SMEM_BYTES>>>(attn, wo, o, bo, M, HID, HID, 0);

    ln_kernel<<<M, 256>>>(x, bo, g, bl, out);

    (void)n_in; (void)out_size;
}

// round 6
// speedup vs baseline: 1.4126x; 1.4126x over previous
#include <cuda_runtime.h>
#include <mma.h>
#include <math.h>
#include <cstdint>

using namespace nvcuda;

#define HID    2304
#define HALF_D 1152
#define NHEADS 16
#define DH     144
#define SLEN   2048
#define MMAX   8192

// -------- scratch (static device globals; no runtime allocation) ----------
__device__ float g_q[(size_t)MMAX * HID];
__device__ float g_k[(size_t)MMAX * HID];
__device__ float g_v[(size_t)MMAX * HID];
__device__ float g_attn[(size_t)MMAX * HID];
__device__ float g_o[(size_t)MMAX * HID];
__device__ float g_cos[SLEN * HALF_D];
__device__ float g_sin[SLEN * HALF_D];
__device__ double g_omega[HALF_D];

// ---------------------------------------------------------------------------
// RoPE tables. Omega in double, then double angle reduction + float sincos.
// ---------------------------------------------------------------------------
__global__ void build_omega_kernel() {
    int i = blockIdx.x * blockDim.x + threadIdx.x;
    if (i < HALF_D) {
        double scale = (2.0 * (double)i) / (double)HID;
        g_omega[i] = exp(-scale * log(10000.0));
    }
}

__global__ void build_rope_kernel() {
    int idx = blockIdx.x * blockDim.x + threadIdx.x;
    if (idx >= SLEN * HALF_D) return;
    int pos = idx / HALF_D;
    int i   = idx - pos * HALF_D;
    double ang = (double)pos * g_omega[i];
    double n = floor(ang * 0.15915494309189535);
    double r = ang - n * 6.283185307179586476925286766559;
    float s, c;
    sincosf((float)r, &s, &c);
    g_cos[idx] = c;
    g_sin[idx] = s;
}

// ---------------------------------------------------------------------------
// cp.async helpers
// ---------------------------------------------------------------------------
__device__ __forceinline__ void cp_async16(uint32_t dst, const float* src) {
    asm volatile("cp.async.cg.shared.global [%0], [%1], 16;\n" :: "r"(dst), "l"(src));
}
__device__ __forceinline__ void cp_commit() {
    asm volatile("cp.async.commit_group;\n");
}
__device__ __forceinline__ void cp_wait1() {
    asm volatile("cp.async.wait_group 1;\n");
}
__device__ __forceinline__ void cp_wait0() {
    asm volatile("cp.async.wait_group 0;\n");
}

// ---------------------------------------------------------------------------
// C[M,N] = A[M,K] @ B[N,K]^T via tf32 wmma, fragment double-buffering.
// CTA tile 128x256x32, 3-stage cp.async pipeline, 8 warps (2x4), 64x64/warp.
// MODE: 0 = direct store; 1 = +bias; 2 = +bias then RoPE.
// ---------------------------------------------------------------------------
#define BM 128
#define BN 256
#define BK 32
#define LDS_PAD 40
#define STAGE_FLOATS ((BM + BN) * LDS_PAD)        // 15360 floats
#define GEMM_SMEM_BYTES (3 * STAGE_FLOATS * 4)    // 184320 B
#define LDC 260

typedef wmma::fragment<wmma::matrix_a, 16, 16, 8, wmma::precision::tf32, wmma::row_major> FragA;
typedef wmma::fragment<wmma::matrix_b, 16, 16, 8, wmma::precision::tf32, wmma::col_major> FragB;
typedef wmma::fragment<wmma::accumulator, 16, 16, 8, float> FragC;

__device__ __forceinline__ void load_stage(const float* __restrict__ A,
                                           const float* __restrict__ B,
                                           int K, int bm, int bn, int k0,
                                           float* As, float* Bs, int tid) {
    uint32_t sA = (uint32_t)__cvta_generic_to_shared(As);
    uint32_t sB = (uint32_t)__cvta_generic_to_shared(Bs);
    #pragma unroll
    for (int i = 0; i < 4; i++) {
        int e = i * 256 + tid;
        int r = e >> 3;
        int c = (e & 7) * 4;
        cp_async16(sA + (uint32_t)(r * LDS_PAD + c) * 4,
                   A + (size_t)(bm + r) * K + k0 + c);
    }
    #pragma unroll
    for (int i = 0; i < 8; i++) {
        int e = i * 256 + tid;
        int r = e >> 3;
        int c = (e & 7) * 4;
        cp_async16(sB + (uint32_t)(r * LDS_PAD + c) * 4,
                   B + (size_t)(bn + r) * K + k0 + c);
    }
}

__device__ __forceinline__ void load_frags(FragA* af, FragB* bf,
                                           const float* As, const float* Bs,
                                           int wm, int wn, int kk) {
    #pragma unroll
    for (int i = 0; i < 4; i++) {
        wmma::load_matrix_sync(af[i], As + (wm + i * 16) * LDS_PAD + kk, LDS_PAD);
        #pragma unroll
        for (int e = 0; e < af[i].num_elements; e++)
            af[i].x[e] = wmma::__float_to_tf32(af[i].x[e]);
    }
    #pragma unroll
    for (int j = 0; j < 4; j++) {
        wmma::load_matrix_sync(bf[j], Bs + (wn + j * 16) * LDS_PAD + kk, LDS_PAD);
        #pragma unroll
        for (int e = 0; e < bf[j].num_elements; e++)
            bf[j].x[e] = wmma::__float_to_tf32(bf[j].x[e]);
    }
}

template <int MODE>
__global__ __launch_bounds__(256, 1)
void gemm_tf32_kernel(const float* __restrict__ A, const float* __restrict__ B,
                      float* __restrict__ C, const float* __restrict__ bias,
                      int M, int N, int K) {
    extern __shared__ float smem[];

    int bm  = blockIdx.y * BM;
    int bn  = blockIdx.x * BN;
    int tid = threadIdx.x;
    int warp = tid >> 5;
    int wm = (warp >> 2) * 64;
    int wn = (warp & 3) * 64;

    FragC acc[4][4];
    #pragma unroll
    for (int i = 0; i < 4; i++)
        #pragma unroll
        for (int j = 0; j < 4; j++)
            wmma::fill_fragment(acc[i][j], 0.0f);

    FragA af[2][4];
    FragB bf[2][4];

    int kIters = K / BK;

    load_stage(A, B, K, bm, bn, 0, smem, smem + BM * LDS_PAD, tid);
    cp_commit();
    load_stage(A, B, K, bm, bn, BK, smem + STAGE_FLOATS,
               smem + STAGE_FLOATS + BM * LDS_PAD, tid);
    cp_commit();

    int stage = 0;
    for (int kt = 0; kt < kIters; kt++) {
        cp_wait1();
        __syncthreads();

        int nk = kt + 2;
        if (nk < kIters) {
            int ns = nk % 3;
            load_stage(A, B, K, bm, bn, nk * BK,
                       smem + ns * STAGE_FLOATS,
                       smem + ns * STAGE_FLOATS + BM * LDS_PAD, tid);
        }
        cp_commit();

        const float* As = smem + stage * STAGE_FLOATS;
        const float* Bs = As + BM * LDS_PAD;

        // fragment double-buffer: prefetch kk+8 while doing MMAs for kk
        load_frags(af[0], bf[0], As, Bs, wm, wn, 0);
        #pragma unroll
        for (int ks = 0; ks < 4; ks++) {
            int cur = ks & 1;
            if (ks < 3)
                load_frags(af[cur ^ 1], bf[cur ^ 1], As, Bs, wm, wn, (ks + 1) * 8);
            #pragma unroll
            for (int j = 0; j < 4; j++)
                #pragma unroll
                for (int i = 0; i < 4; i++)
                    wmma::mma_sync(acc[i][j], af[cur][i], bf[cur][j], acc[i][j]);
        }

        stage = (stage + 1 == 3) ? 0 : stage + 1;
    }

    if (MODE == 0) {
        #pragma unroll
        for (int i = 0; i < 4; i++)
            #pragma unroll
            for (int j = 0; j < 4; j++)
                wmma::store_matrix_sync(C + (size_t)(bm + wm + i * 16) * N + (bn + wn + j * 16),
                                        acc[i][j], N, wmma::mem_row_major);
        return;
    }

    // fused epilogue: stage C tile in smem (reuse pipeline buffers)
    cp_wait0();
    __syncthreads();
    #pragma unroll
    for (int i = 0; i < 4; i++)
        #pragma unroll
        for (int j = 0; j < 4; j++)
            wmma::store_matrix_sync(smem + (wm + i * 16) * LDC + wn + j * 16,
                                    acc[i][j], LDC, wmma::mem_row_major);
    __syncthreads();

    if (MODE == 1) {
        for (int e = tid; e < BM * (BN / 2); e += 256) {
            int r = e >> 7;
            int p = e & 127;
            int col = bn + 2 * p;
            float v0 = smem[r * LDC + 2 * p]     + bias[col];
            float v1 = smem[r * LDC + 2 * p + 1] + bias[col + 1];
            float* dst = C + (size_t)(bm + r) * N + col;
            dst[0] = v0;
            dst[1] = v1;
        }
    } else {
        for (int e = tid; e < BM * (BN / 2); e += 256) {
            int r = e >> 7;
            int p = e & 127;
            int col = bn + 2 * p;
            int i = col >> 1;
            int pos = (bm + r) & (SLEN - 1);
            float c = g_cos[pos * HALF_D + i];
            float s = g_sin[pos * HALF_D + i];
            float x0 = smem[r * LDC + 2 * p]     + bias[col];
            float x1 = smem[r * LDC + 2 * p + 1] + bias[col + 1];
            float* dst = C + (size_t)(bm + r) * N + col;
            dst[0] = c * x0 - s * x1;
            dst[1] = s * x0 + c * x1;
        }
    }
}

// ======================= head-mixing attention =============================
__global__ __launch_bounds__(256)
void attention_kernel(int M) {
    __shared__ float qt[DH * NHEADS];
    __shared__ float kt[DH * NHEADS];
    __shared__ float vs[HID];
    __shared__ float w[NHEADS * NHEADS];

    int p = blockIdx.x;
    int t = threadIdx.x;
    const float* qrow = g_q + (size_t)p * HID;
    const float* krow = g_k + (size_t)p * HID;
    const float* vrow = g_v + (size_t)p * HID;

    for (int c = t; c < HID; c += 256) {
        int n = c / DH;
        int j = c - n * DH;
        qt[j * NHEADS + n] = qrow[c];
        kt[j * NHEADS + n] = krow[c];
        vs[c] = vrow[c];
    }
    __syncthreads();

    {
        int m = t >> 4;
        int n = t & 15;
        float acc = 0.0f;
        #pragma unroll 8
        for (int j = 0; j < DH; j++)
            acc += qt[j * NHEADS + n] * kt[j * NHEADS + m];
        w[n * NHEADS + m] = acc * (1.0f / 12.0f);
    }
    __syncthreads();

    if (t < NHEADS) {
        float mx = -1e30f;
        #pragma unroll
        for (int m = 0; m < NHEADS; m++) mx = fmaxf(mx, w[t * NHEADS + m]);
        float sum = 0.0f;
        #pragma unroll
        for (int m = 0; m < NHEADS; m++) {
            float e = expf(w[t * NHEADS + m] - mx);
            w[t * NHEADS + m] = e;
            sum += e;
        }
        float inv = 1.0f / sum;
        #pragma unroll
        for (int m = 0; m < NHEADS; m++) w[t * NHEADS + m] *= inv;
    }
    __syncthreads();

    float* arow = g_attn + (size_t)p * HID;
    for (int c = t; c < HID; c += 256) {
        int n = c / DH;
        int j = c - n * DH;
        float acc = 0.0f;
        #pragma unroll
        for (int m = 0; m < NHEADS; m++)
            acc += w[n * NHEADS + m] * vs[m * DH + j];
        arow[c] = acc;
    }
}

// ======================= residual + LayerNorm ==============================
__device__ __forceinline__ float block_sum(float v, float* red) {
    #pragma unroll
    for (int o = 16; o > 0; o >>= 1) v += __shfl_xor_sync(0xFFFFFFFFu, v, o);
    int warp = threadIdx.x >> 5, lane = threadIdx.x & 31;
    if (lane == 0) red[warp] = v;
    __syncthreads();
    if (warp == 0) {
        float x = (lane < 8) ? red[lane] : 0.0f;
        #pragma unroll
        for (int o = 4; o > 0; o >>= 1) x += __shfl_xor_sync(0xFFFFFFFFu, x, o);
        if (lane == 0) red[0] = x;
    }
    __syncthreads();
    float r = red[0];
    __syncthreads();
    return r;
}

__global__ __launch_bounds__(256)
void ln_kernel(const float* __restrict__ x, const float* __restrict__ bo,
               const float* __restrict__ gamma, const float* __restrict__ beta,
               float* __restrict__ out) {
    __shared__ float ybuf[HID];
    __shared__ float red[8];

    int row = blockIdx.x;
    int t = threadIdx.x;
    const float* xr = x + (size_t)row * HID;
    const float* orow = g_o + (size_t)row * HID;

    float s = 0.0f;
    for (int c = t; c < HID; c += 256) {
        float y = xr[c] + orow[c] + bo[c];
        ybuf[c] = y;
        s += y;
    }
    float total = block_sum(s, red);
    float mu = total * (1.0f / (float)HID);

    float vsum = 0.0f;
    for (int c = t; c < HID; c += 256) {
        float dy = ybuf[c] - mu;
        vsum += dy * dy;
    }
    float vtot = block_sum(vsum, red);
    float var = vtot * (1.0f / (float)HID);
    float rstd = rsqrtf(var + 1e-5f);

    float* orow_out = out + (size_t)row * HID;
    for (int c = t; c < HID; c += 256) {
        orow_out[c] = (ybuf[c] - mu) * rstd * gamma[c] + beta[c];
    }
}

// ---------------------------------------------------------------------------
extern "C" void kernel_launch(void* const* d_in, const int* in_sizes, int n_in,
                              void* d_out, int out_size) {
    const float* x  = (const float*)d_in[0];
    const float* wq = (const float*)d_in[1];
    const float* bq = (const float*)d_in[2];
    const float* wk = (const float*)d_in[3];
    const float* bk = (const float*)d_in[4];
    const float* wv = (const float*)d_in[5];
    const float* bv = (const float*)d_in[6];
    const float* wo = (const float*)d_in[7];
    const float* bo = (const float*)d_in[8];
    const float* g  = (const float*)d_in[9];
    const float* bl = (const float*)d_in[10];
    float* out = (float*)d_out;

    int M = in_sizes[0] / HID;   // b*s = 8192

    float *q, *k, *v, *attn, *o;
    cudaGetSymbolAddress((void**)&q,    g_q);
    cudaGetSymbolAddress((void**)&k,    g_k);
    cudaGetSymbolAddress((void**)&v,    g_v);
    cudaGetSymbolAddress((void**)&attn, g_attn);
    cudaGetSymbolAddress((void**)&o,    g_o);

    static int smem_set = 0;
    if (!smem_set) {
        cudaFuncSetAttribute(gemm_tf32_kernel<0>,
                             cudaFuncAttributeMaxDynamicSharedMemorySize, GEMM_SMEM_BYTES);
        cudaFuncSetAttribute(gemm_tf32_kernel<1>,
                             cudaFuncAttributeMaxDynamicSharedMemorySize, GEMM_SMEM_BYTES);
        cudaFuncSetAttribute(gemm_tf32_kernel<2>,
                             cudaFuncAttributeMaxDynamicSharedMemorySize, GEMM_SMEM_BYTES);
        smem_set = 1;
    }

    build_omega_kernel<<<(HALF_D + 255) / 256, 256>>>();
    build_rope_kernel<<<(SLEN * HALF_D + 255) / 256, 256>>>();

    dim3 ggrid(HID / BN, M / BM);   // 9 x 64
    gemm_tf32_kernel<2><<<ggrid, 256, GEMM_SMEM_BYTES>>>(x, wq, q, bq, M, HID, HID);
    gemm_tf32_kernel<2><<<ggrid, 256, GEMM_SMEM_BYTES>>>(x, wk, k, bk, M, HID, HID);
    gemm_tf32_kernel<1><<<ggrid, 256, GEMM_SMEM_BYTES>>>(x, wv, v, bv, M, HID, HID);

    attention_kernel<<<M, 256>>>(M);

    gemm_tf32_kernel<0><<<ggrid, 256, GEMM_SMEM_BYTES>>>(attn, wo, o, bo, M, HID, HID);

    ln_kernel<<<M, 256>>>(x, bo, g, bl, out);

    (void)n_in; (void)out_size;
}

// round 7
// speedup vs baseline: 3.1820x; 2.2525x over previous
#include <cuda_runtime.h>
#include <math.h>
#include <cstdint>

#define HID    2304
#define HALF_D 1152
#define NHEADS 16
#define DH     144
#define SLEN   2048
#define MMAX   8192

// -------- scratch (static device globals; no runtime allocation) ----------
__device__ float g_q[(size_t)MMAX * HID];
__device__ float g_k[(size_t)MMAX * HID];
__device__ float g_v[(size_t)MMAX * HID];
__device__ float g_attn[(size_t)MMAX * HID];
__device__ float g_o[(size_t)MMAX * HID];
__device__ float g_cos[SLEN * HALF_D];
__device__ float g_sin[SLEN * HALF_D];
__device__ double g_omega[HALF_D];

// ---------------------------------------------------------------------------
// RoPE tables.
// ---------------------------------------------------------------------------
__global__ void build_omega_kernel() {
    int i = blockIdx.x * blockDim.x + threadIdx.x;
    if (i < HALF_D) {
        double scale = (2.0 * (double)i) / (double)HID;
        g_omega[i] = exp(-scale * log(10000.0));
    }
}

__global__ void build_rope_kernel() {
    int idx = blockIdx.x * blockDim.x + threadIdx.x;
    if (idx >= SLEN * HALF_D) return;
    int pos = idx / HALF_D;
    int i   = idx - pos * HALF_D;
    double ang = (double)pos * g_omega[i];
    double n = floor(ang * 0.15915494309189535);
    double r = ang - n * 6.283185307179586476925286766559;
    float s, c;
    sincosf((float)r, &s, &c);
    g_cos[idx] = c;
    g_sin[idx] = s;
}

// ---------------------------------------------------------------------------
// PTX helpers
// ---------------------------------------------------------------------------
__device__ __forceinline__ void cp_async16(uint32_t dst, const float* src) {
    asm volatile("cp.async.cg.shared.global [%0], [%1], 16;\n" :: "r"(dst), "l"(src));
}
__device__ __forceinline__ void cp_commit() {
    asm volatile("cp.async.commit_group;\n");
}
__device__ __forceinline__ void cp_wait1() {
    asm volatile("cp.async.wait_group 1;\n");
}

#define LDSM4(r0, r1, r2, r3, addr) \
    asm volatile("ldmatrix.sync.aligned.m8n8.x4.shared.b16 {%0,%1,%2,%3}, [%4];" \
                 : "=r"(r0), "=r"(r1), "=r"(r2), "=r"(r3) : "r"(addr))

#define CVT_TF32(x) asm("cvt.rna.tf32.f32 %0, %0;" : "+r"(x))

#define MMA_TF32(d, a0, a1, a2, a3, b0, b1) \
    asm volatile("mma.sync.aligned.m16n8k8.row.col.f32.tf32.tf32.f32 " \
                 "{%0,%1,%2,%3}, {%4,%5,%6,%7}, {%8,%9}, {%0,%1,%2,%3};" \
                 : "+f"((d)[0]), "+f"((d)[1]), "+f"((d)[2]), "+f"((d)[3]) \
                 : "r"(a0), "r"(a1), "r"(a2), "r"(a3), "r"(b0), "r"(b1))

// ---------------------------------------------------------------------------
// C[M,N] = A[M,K] @ B[N,K]^T via raw mma.sync tf32 + ldmatrix.
// CTA tile 128x256x32, 3-stage cp.async pipeline, 8 warps (2x4), 64x64/warp.
// smem rows are 128B (32 f32) with SW128 swizzle: conflict-free cp.async + LDSM.
// MODE: 0 = direct store; 1 = +bias; 2 = +bias then RoPE (register epilogue).
// ---------------------------------------------------------------------------
#define BM 128
#define BN 256
#define BK 32
#define A_BYTES (BM * 128)                 // 16384
#define B_BYTES (BN * 128)                 // 32768
#define STAGE_BYTES (A_BYTES + B_BYTES)    // 49152
#define GEMM_SMEM_BYTES (3 * STAGE_BYTES)  // 147456

__device__ __forceinline__ void load_stage(const float* __restrict__ A,
                                           const float* __restrict__ B,
                                           int K, int bm, int bn, int k0,
                                           uint32_t stg, int tid) {
    #pragma unroll
    for (int i = 0; i < 4; i++) {              // A: 1024 chunks of 16B
        int e = i * 256 + tid;
        int r = e >> 3;
        int cb = (e & 7) * 16;                 // byte within 128B row
        cp_async16(stg + r * 128 + (cb ^ ((r & 7) << 4)),
                   A + (size_t)(bm + r) * K + k0 + (e & 7) * 4);
    }
    #pragma unroll
    for (int i = 0; i < 8; i++) {              // B: 2048 chunks
        int e = i * 256 + tid;
        int r = e >> 3;
        int cb = (e & 7) * 16;
        cp_async16(stg + A_BYTES + r * 128 + (cb ^ ((r & 7) << 4)),
                   B + (size_t)(bn + r) * K + k0 + (e & 7) * 4);
    }
}

template <int MODE>
__global__ __launch_bounds__(256, 1)
void gemm_tf32_kernel(const float* __restrict__ A, const float* __restrict__ B,
                      float* __restrict__ C, const float* __restrict__ bias,
                      int M, int N, int K) {
    extern __shared__ char smem[];
    uint32_t sbase;
    asm("{ .reg .u64 t; cvta.to.shared.u64 t, %1; cvt.u32.u64 %0, t; }"
        : "=r"(sbase) : "l"(smem));

    const int tid  = threadIdx.x;
    const int warp = tid >> 5;
    const int lane = tid & 31;
    const int bm = blockIdx.y * BM;
    const int bn = blockIdx.x * BN;
    const int wm = (warp >> 2) * 64;
    const int wn = (warp & 3) * 64;

    const int lr = lane & 7;           // row within 8-row ldmatrix tile
    const int lh = (lane >> 3) & 1;    // selector bit (lanes 8-15, 24-31)
    const int lc = lane >> 4;          // selector bit (lanes 16-31)

    // ldmatrix row indices + swizzle constants (per thread, stage-invariant)
    // A x4 tiles: (m0..7,kL),(m8..15,kL),(m0..7,kH),(m8..15,kH)
    //   row = wm + mb*16 + lr + lh*8 ; chunk sel = lc
    // B x4 tiles: (n0..7,kL),(n0..7,kH),(n8..15,kL),(n8..15,kH)
    //   row = wn + j*16 + lr + lc*8 ; chunk sel = lh
    int rowA[4], rowB[4];
    #pragma unroll
    for (int mb = 0; mb < 4; mb++) rowA[mb] = wm + mb * 16 + lr + lh * 8;
    #pragma unroll
    for (int j = 0; j < 4; j++)    rowB[j] = wn + j * 16 + lr + lc * 8;

    float acc[4][8][4];
    #pragma unroll
    for (int mb = 0; mb < 4; mb++)
        #pragma unroll
        for (int nb = 0; nb < 8; nb++)
            #pragma unroll
            for (int e = 0; e < 4; e++) acc[mb][nb][e] = 0.0f;

    const int kIters = K / BK;   // 72

    load_stage(A, B, K, bm, bn, 0, sbase, tid);
    cp_commit();
    load_stage(A, B, K, bm, bn, BK, sbase + STAGE_BYTES, tid);
    cp_commit();

    int stage = 0;
    for (int kt = 0; kt < kIters; kt++) {
        cp_wait1();
        __syncthreads();

        int nk = kt + 2;
        if (nk < kIters)
            load_stage(A, B, K, bm, bn, nk * BK,
                       sbase + (nk % 3) * STAGE_BYTES, tid);
        cp_commit();

        const uint32_t stg = sbase + stage * STAGE_BYTES;

        #pragma unroll
        for (int kk = 0; kk < 4; kk++) {       // 4 k8-steps per stage
            const int kbL = kk * 32;           // byte offset of k-slab in row
            uint32_t a[4][4], b[4][4];
            #pragma unroll
            for (int mb = 0; mb < 4; mb++) {
                uint32_t ad = stg + rowA[mb] * 128 +
                              ((kbL + lc * 16) ^ ((rowA[mb] & 7) << 4));
                LDSM4(a[mb][0], a[mb][1], a[mb][2], a[mb][3], ad);
            }
            #pragma unroll
            for (int j = 0; j < 4; j++) {
                uint32_t bd = stg + A_BYTES + rowB[j] * 128 +
                              ((kbL + lh * 16) ^ ((rowB[j] & 7) << 4));
                LDSM4(b[j][0], b[j][1], b[j][2], b[j][3], bd);
            }
            #pragma unroll
            for (int mb = 0; mb < 4; mb++) {
                CVT_TF32(a[mb][0]); CVT_TF32(a[mb][1]);
                CVT_TF32(a[mb][2]); CVT_TF32(a[mb][3]);
            }
            #pragma unroll
            for (int j = 0; j < 4; j++) {
                CVT_TF32(b[j][0]); CVT_TF32(b[j][1]);
                CVT_TF32(b[j][2]); CVT_TF32(b[j][3]);
            }
            #pragma unroll
            for (int mb = 0; mb < 4; mb++)
                #pragma unroll
                for (int j = 0; j < 4; j++) {
                    MMA_TF32(acc[mb][2 * j],     a[mb][0], a[mb][1], a[mb][2], a[mb][3],
                             b[j][0], b[j][1]);
                    MMA_TF32(acc[mb][2 * j + 1], a[mb][0], a[mb][1], a[mb][2], a[mb][3],
                             b[j][2], b[j][3]);
                }
        }

        stage = (stage + 1 == 3) ? 0 : stage + 1;
    }

    // -------- register epilogue: bias / RoPE, st.global.v2 ---------
    #pragma unroll
    for (int mb = 0; mb < 4; mb++) {
        const int r0 = bm + wm + mb * 16 + (lane >> 2);
        #pragma unroll
        for (int nb = 0; nb < 8; nb++) {
            const int gc = bn + wn + nb * 8 + (lane & 3) * 2;
            float x0 = acc[mb][nb][0], x1 = acc[mb][nb][1];
            float y0 = acc[mb][nb][2], y1 = acc[mb][nb][3];
            if (MODE >= 1) {
                float2 bb = *(const float2*)(bias + gc);
                x0 += bb.x; x1 += bb.y;
                y0 += bb.x; y1 += bb.y;
            }
            if (MODE == 2) {
                const int i = gc >> 1;
                const int p0 = r0 & (SLEN - 1);
                const int p1 = (r0 + 8) & (SLEN - 1);
                float c0 = g_cos[p0 * HALF_D + i], s0 = g_sin[p0 * HALF_D + i];
                float c1 = g_cos[p1 * HALF_D + i], s1 = g_sin[p1 * HALF_D + i];
                float t0 = c0 * x0 - s0 * x1;
                float t1 = s0 * x0 + c0 * x1;
                x0 = t0; x1 = t1;
                t0 = c1 * y0 - s1 * y1;
                t1 = s1 * y0 + c1 * y1;
                y0 = t0; y1 = t1;
            }
            *(float2*)(C + (size_t)r0 * N + gc)       = make_float2(x0, x1);
            *(float2*)(C + (size_t)(r0 + 8) * N + gc) = make_float2(y0, y1);
        }
    }
}

// ======================= head-mixing attention =============================
__global__ __launch_bounds__(256)
void attention_kernel(int M) {
    __shared__ float qt[DH * NHEADS];
    __shared__ float kt[DH * NHEADS];
    __shared__ float vs[HID];
    __shared__ float w[NHEADS * NHEADS];

    int p = blockIdx.x;
    int t = threadIdx.x;
    const float* qrow = g_q + (size_t)p * HID;
    const float* krow = g_k + (size_t)p * HID;
    const float* vrow = g_v + (size_t)p * HID;

    for (int c = t; c < HID; c += 256) {
        int n = c / DH;
        int j = c - n * DH;
        qt[j * NHEADS + n] = qrow[c];
        kt[j * NHEADS + n] = krow[c];
        vs[c] = vrow[c];
    }
    __syncthreads();

    {
        int m = t >> 4;
        int n = t & 15;
        float acc = 0.0f;
        #pragma unroll 8
        for (int j = 0; j < DH; j++)
            acc += qt[j * NHEADS + n] * kt[j * NHEADS + m];
        w[n * NHEADS + m] = acc * (1.0f / 12.0f);
    }
    __syncthreads();

    if (t < NHEADS) {
        float mx = -1e30f;
        #pragma unroll
        for (int m = 0; m < NHEADS; m++) mx = fmaxf(mx, w[t * NHEADS + m]);
        float sum = 0.0f;
        #pragma unroll
        for (int m = 0; m < NHEADS; m++) {
            float e = expf(w[t * NHEADS + m] - mx);
            w[t * NHEADS + m] = e;
            sum += e;
        }
        float inv = 1.0f / sum;
        #pragma unroll
        for (int m = 0; m < NHEADS; m++) w[t * NHEADS + m] *= inv;
    }
    __syncthreads();

    float* arow = g_attn + (size_t)p * HID;
    for (int c = t; c < HID; c += 256) {
        int n = c / DH;
        int j = c - n * DH;
        float acc = 0.0f;
        #pragma unroll
        for (int m = 0; m < NHEADS; m++)
            acc += w[n * NHEADS + m] * vs[m * DH + j];
        arow[c] = acc;
    }
}

// ======================= residual + LayerNorm ==============================
__device__ __forceinline__ float block_sum(float v, float* red) {
    #pragma unroll
    for (int o = 16; o > 0; o >>= 1) v += __shfl_xor_sync(0xFFFFFFFFu, v, o);
    int warp = threadIdx.x >> 5, lane = threadIdx.x & 31;
    if (lane == 0) red[warp] = v;
    __syncthreads();
    if (warp == 0) {
        float x = (lane < 8) ? red[lane] : 0.0f;
        #pragma unroll
        for (int o = 4; o > 0; o >>= 1) x += __shfl_xor_sync(0xFFFFFFFFu, x, o);
        if (lane == 0) red[0] = x;
    }
    __syncthreads();
    float r = red[0];
    __syncthreads();
    return r;
}

__global__ __launch_bounds__(256)
void ln_kernel(const float* __restrict__ x, const float* __restrict__ bo,
               const float* __restrict__ gamma, const float* __restrict__ beta,
               float* __restrict__ out) {
    __shared__ float ybuf[HID];
    __shared__ float red[8];

    int row = blockIdx.x;
    int t = threadIdx.x;
    const float* xr = x + (size_t)row * HID;
    const float* orow = g_o + (size_t)row * HID;

    float s = 0.0f;
    for (int c = t; c < HID; c += 256) {
        float y = xr[c] + orow[c] + bo[c];
        ybuf[c] = y;
        s += y;
    }
    float total = block_sum(s, red);
    float mu = total * (1.0f / (float)HID);

    float vsum = 0.0f;
    for (int c = t; c < HID; c += 256) {
        float dy = ybuf[c] - mu;
        vsum += dy * dy;
    }
    float vtot = block_sum(vsum, red);
    float var = vtot * (1.0f / (float)HID);
    float rstd = rsqrtf(var + 1e-5f);

    float* orow_out = out + (size_t)row * HID;
    for (int c = t; c < HID; c += 256) {
        orow_out[c] = (ybuf[c] - mu) * rstd * gamma[c] + beta[c];
    }
}

// ---------------------------------------------------------------------------
extern "C" void kernel_launch(void* const* d_in, const int* in_sizes, int n_in,
                              void* d_out, int out_size) {
    const float* x  = (const float*)d_in[0];
    const float* wq = (const float*)d_in[1];
    const float* bq = (const float*)d_in[2];
    const float* wk = (const float*)d_in[3];
    const float* bk = (const float*)d_in[4];
    const float* wv = (const float*)d_in[5];
    const float* bv = (const float*)d_in[6];
    const float* wo = (const float*)d_in[7];
    const float* bo = (const float*)d_in[8];
    const float* g  = (const float*)d_in[9];
    const float* bl = (const float*)d_in[10];
    float* out = (float*)d_out;

    int M = in_sizes[0] / HID;   // b*s = 8192

    float *q, *k, *v, *attn, *o;
    cudaGetSymbolAddress((void**)&q,    g_q);
    cudaGetSymbolAddress((void**)&k,    g_k);
    cudaGetSymbolAddress((void**)&v,    g_v);
    cudaGetSymbolAddress((void**)&attn, g_attn);
    cudaGetSymbolAddress((void**)&o,    g_o);

    static int smem_set = 0;
    if (!smem_set) {
        cudaFuncSetAttribute(gemm_tf32_kernel<0>,
                             cudaFuncAttributeMaxDynamicSharedMemorySize, GEMM_SMEM_BYTES);
        cudaFuncSetAttribute(gemm_tf32_kernel<1>,
                             cudaFuncAttributeMaxDynamicSharedMemorySize, GEMM_SMEM_BYTES);
        cudaFuncSetAttribute(gemm_tf32_kernel<2>,
                             cudaFuncAttributeMaxDynamicSharedMemorySize, GEMM_SMEM_BYTES);
        smem_set = 1;
    }

    build_omega_kernel<<<(HALF_D + 255) / 256, 256>>>();
    build_rope_kernel<<<(SLEN * HALF_D + 255) / 256, 256>>>();

    dim3 ggrid(HID / BN, M / BM);   // 9 x 64
    gemm_tf32_kernel<2><<<ggrid, 256, GEMM_SMEM_BYTES>>>(x, wq, q, bq, M, HID, HID);
    gemm_tf32_kernel<2><<<ggrid, 256, GEMM_SMEM_BYTES>>>(x, wk, k, bk, M, HID, HID);
    gemm_tf32_kernel<1><<<ggrid, 256, GEMM_SMEM_BYTES>>>(x, wv, v, bv, M, HID, HID);

    attention_kernel<<<M, 256>>>(M);

    gemm_tf32_kernel<0><<<ggrid, 256, GEMM_SMEM_BYTES>>>(attn, wo, o, bo, M, HID, HID);

    ln_kernel<<<M, 256>>>(x, bo, g, bl, out);

    (void)n_in; (void)out_size;
}

// round 8
// speedup vs baseline: 3.3952x; 1.0670x over previous
#include <cuda_runtime.h>
#include <math.h>
#include <cstdint>

#define HID    2304
#define HALF_D 1152
#define NHEADS 16
#define DH     144
#define SLEN   2048
#define MMAX   8192

// -------- scratch (static device globals; no runtime allocation) ----------
__device__ float g_q[(size_t)MMAX * HID];
__device__ float g_k[(size_t)MMAX * HID];
__device__ float g_v[(size_t)MMAX * HID];
__device__ float g_attn[(size_t)MMAX * HID];
__device__ float g_o[(size_t)MMAX * HID];
__device__ float g_xr[(size_t)MMAX * HID];      // tf32-rounded x
__device__ float g_wqr[(size_t)HID * HID];      // tf32-rounded weights
__device__ float g_wkr[(size_t)HID * HID];
__device__ float g_wvr[(size_t)HID * HID];
__device__ float g_wor[(size_t)HID * HID];
__device__ float g_cos[SLEN * HALF_D];
__device__ float g_sin[SLEN * HALF_D];
__device__ double g_omega[HALF_D];

#define CVT_TF32(x) asm("cvt.rna.tf32.f32 %0, %0;" : "+r"(x))

// ---------------------------------------------------------------------------
// RoPE tables.
// ---------------------------------------------------------------------------
__global__ void build_omega_kernel() {
    int i = blockIdx.x * blockDim.x + threadIdx.x;
    if (i < HALF_D) {
        double scale = (2.0 * (double)i) / (double)HID;
        g_omega[i] = exp(-scale * log(10000.0));
    }
}

__global__ void build_rope_kernel() {
    int idx = blockIdx.x * blockDim.x + threadIdx.x;
    if (idx >= SLEN * HALF_D) return;
    int pos = idx / HALF_D;
    int i   = idx - pos * HALF_D;
    double ang = (double)pos * g_omega[i];
    double n = floor(ang * 0.15915494309189535);
    double r = ang - n * 6.283185307179586476925286766559;
    float s, c;
    sincosf((float)r, &s, &c);
    g_cos[idx] = c;
    g_sin[idx] = s;
}

// ---------------------------------------------------------------------------
// Pre-round a tensor to tf32 precision (rna), vectorized.
// ---------------------------------------------------------------------------
__global__ void round_tf32_kernel(const float* __restrict__ in,
                                  float* __restrict__ out, int n4) {
    int i = blockIdx.x * blockDim.x + threadIdx.x;
    if (i >= n4) return;
    float4 v = ((const float4*)in)[i];
    uint32_t a = __float_as_uint(v.x), b = __float_as_uint(v.y);
    uint32_t c = __float_as_uint(v.z), d = __float_as_uint(v.w);
    CVT_TF32(a); CVT_TF32(b); CVT_TF32(c); CVT_TF32(d);
    v.x = __uint_as_float(a); v.y = __uint_as_float(b);
    v.z = __uint_as_float(c); v.w = __uint_as_float(d);
    ((float4*)out)[i] = v;
}

// ---------------------------------------------------------------------------
// PTX helpers
// ---------------------------------------------------------------------------
__device__ __forceinline__ void cp_async16(uint32_t dst, const float* src) {
    asm volatile("cp.async.cg.shared.global [%0], [%1], 16;\n" :: "r"(dst), "l"(src));
}
__device__ __forceinline__ void cp_commit() {
    asm volatile("cp.async.commit_group;\n");
}
__device__ __forceinline__ void cp_wait1() {
    asm volatile("cp.async.wait_group 1;\n");
}

#define LDSM4(r0, r1, r2, r3, addr) \
    asm volatile("ldmatrix.sync.aligned.m8n8.x4.shared.b16 {%0,%1,%2,%3}, [%4];" \
                 : "=r"(r0), "=r"(r1), "=r"(r2), "=r"(r3) : "r"(addr))

#define MMA_TF32(d, a0, a1, a2, a3, b0, b1) \
    asm volatile("mma.sync.aligned.m16n8k8.row.col.f32.tf32.tf32.f32 " \
                 "{%0,%1,%2,%3}, {%4,%5,%6,%7}, {%8,%9}, {%0,%1,%2,%3};" \
                 : "+f"((d)[0]), "+f"((d)[1]), "+f"((d)[2]), "+f"((d)[3]) \
                 : "r"(a0), "r"(a1), "r"(a2), "r"(a3), "r"(b0), "r"(b1))

// ---------------------------------------------------------------------------
// C[M,N] = A[M,K] @ B[N,K]^T via raw mma.sync tf32 + ldmatrix.
// Inputs MUST be pre-rounded to tf32 precision (no in-loop cvt).
// CTA tile 128x256x32, 3-stage cp.async pipeline, 8 warps (2x4), 64x64/warp.
// MODE: 0 = direct store; 1 = +bias; 2 = +bias then RoPE (register epilogue).
// ---------------------------------------------------------------------------
#define BM 128
#define BN 256
#define BK 32
#define A_BYTES (BM * 128)                 // 16384
#define B_BYTES (BN * 128)                 // 32768
#define STAGE_BYTES (A_BYTES + B_BYTES)    // 49152
#define GEMM_SMEM_BYTES (3 * STAGE_BYTES)  // 147456

__device__ __forceinline__ void load_stage(const float* __restrict__ A,
                                           const float* __restrict__ B,
                                           int K, int bm, int bn, int k0,
                                           uint32_t stg, int tid) {
    #pragma unroll
    for (int i = 0; i < 4; i++) {              // A: 1024 chunks of 16B
        int e = i * 256 + tid;
        int r = e >> 3;
        int cb = (e & 7) * 16;
        cp_async16(stg + r * 128 + (cb ^ ((r & 7) << 4)),
                   A + (size_t)(bm + r) * K + k0 + (e & 7) * 4);
    }
    #pragma unroll
    for (int i = 0; i < 8; i++) {              // B: 2048 chunks
        int e = i * 256 + tid;
        int r = e >> 3;
        int cb = (e & 7) * 16;
        cp_async16(stg + A_BYTES + r * 128 + (cb ^ ((r & 7) << 4)),
                   B + (size_t)(bn + r) * K + k0 + (e & 7) * 4);
    }
}

template <int MODE>
__global__ __launch_bounds__(256, 1)
void gemm_tf32_kernel(const float* __restrict__ A, const float* __restrict__ B,
                      float* __restrict__ C, const float* __restrict__ bias,
                      int M, int N, int K) {
    extern __shared__ char smem[];
    uint32_t sbase;
    asm("{ .reg .u64 t; cvta.to.shared.u64 t, %1; cvt.u32.u64 %0, t; }"
        : "=r"(sbase) : "l"(smem));

    const int tid  = threadIdx.x;
    const int warp = tid >> 5;
    const int lane = tid & 31;
    const int bm = blockIdx.y * BM;
    const int bn = blockIdx.x * BN;
    const int wm = (warp >> 2) * 64;
    const int wn = (warp & 3) * 64;

    const int lr = lane & 7;
    const int lh = (lane >> 3) & 1;
    const int lc = lane >> 4;

    int rowA[4], rowB[4];
    #pragma unroll
    for (int mb = 0; mb < 4; mb++) rowA[mb] = wm + mb * 16 + lr + lh * 8;
    #pragma unroll
    for (int j = 0; j < 4; j++)    rowB[j] = wn + j * 16 + lr + lc * 8;

    float acc[4][8][4];
    #pragma unroll
    for (int mb = 0; mb < 4; mb++)
        #pragma unroll
        for (int nb = 0; nb < 8; nb++)
            #pragma unroll
            for (int e = 0; e < 4; e++) acc[mb][nb][e] = 0.0f;

    const int kIters = K / BK;   // 72

    load_stage(A, B, K, bm, bn, 0, sbase, tid);
    cp_commit();
    load_stage(A, B, K, bm, bn, BK, sbase + STAGE_BYTES, tid);
    cp_commit();

    int stage = 0;
    for (int kt = 0; kt < kIters; kt++) {
        cp_wait1();
        __syncthreads();

        int nk = kt + 2;
        if (nk < kIters)
            load_stage(A, B, K, bm, bn, nk * BK,
                       sbase + (nk % 3) * STAGE_BYTES, tid);
        cp_commit();

        const uint32_t stg = sbase + stage * STAGE_BYTES;

        #pragma unroll
        for (int kk = 0; kk < 4; kk++) {
            const int kbL = kk * 32;
            uint32_t a[4][4], b[4][4];
            #pragma unroll
            for (int mb = 0; mb < 4; mb++) {
                uint32_t ad = stg + rowA[mb] * 128 +
                              ((kbL + lc * 16) ^ ((rowA[mb] & 7) << 4));
                LDSM4(a[mb][0], a[mb][1], a[mb][2], a[mb][3], ad);
            }
            #pragma unroll
            for (int j = 0; j < 4; j++) {
                uint32_t bd = stg + A_BYTES + rowB[j] * 128 +
                              ((kbL + lh * 16) ^ ((rowB[j] & 7) << 4));
                LDSM4(b[j][0], b[j][1], b[j][2], b[j][3], bd);
            }
            #pragma unroll
            for (int mb = 0; mb < 4; mb++)
                #pragma unroll
                for (int j = 0; j < 4; j++) {
                    MMA_TF32(acc[mb][2 * j],     a[mb][0], a[mb][1], a[mb][2], a[mb][3],
                             b[j][0], b[j][1]);
                    MMA_TF32(acc[mb][2 * j + 1], a[mb][0], a[mb][1], a[mb][2], a[mb][3],
                             b[j][2], b[j][3]);
                }
        }

        stage = (stage + 1 == 3) ? 0 : stage + 1;
    }

    // -------- register epilogue: bias / RoPE, st.global.v2 ---------
    #pragma unroll
    for (int mb = 0; mb < 4; mb++) {
        const int r0 = bm + wm + mb * 16 + (lane >> 2);
        #pragma unroll
        for (int nb = 0; nb < 8; nb++) {
            const int gc = bn + wn + nb * 8 + (lane & 3) * 2;
            float x0 = acc[mb][nb][0], x1 = acc[mb][nb][1];
            float y0 = acc[mb][nb][2], y1 = acc[mb][nb][3];
            if (MODE >= 1) {
                float2 bb = *(const float2*)(bias + gc);
                x0 += bb.x; x1 += bb.y;
                y0 += bb.x; y1 += bb.y;
            }
            if (MODE == 2) {
                const int i = gc >> 1;
                const int p0 = r0 & (SLEN - 1);
                const int p1 = (r0 + 8) & (SLEN - 1);
                float c0 = g_cos[p0 * HALF_D + i], s0 = g_sin[p0 * HALF_D + i];
                float c1 = g_cos[p1 * HALF_D + i], s1 = g_sin[p1 * HALF_D + i];
                float t0 = c0 * x0 - s0 * x1;
                float t1 = s0 * x0 + c0 * x1;
                x0 = t0; x1 = t1;
                t0 = c1 * y0 - s1 * y1;
                t1 = s1 * y0 + c1 * y1;
                y0 = t0; y1 = t1;
            }
            *(float2*)(C + (size_t)r0 * N + gc)       = make_float2(x0, x1);
            *(float2*)(C + (size_t)(r0 + 8) * N + gc) = make_float2(y0, y1);
        }
    }
}

// ======================= head-mixing attention =============================
// Output is rounded to tf32 at store (feeds the final GEMM).
__global__ __launch_bounds__(256)
void attention_kernel(int M) {
    __shared__ float qt[DH * NHEADS];
    __shared__ float kt[DH * NHEADS];
    __shared__ float vs[HID];
    __shared__ float w[NHEADS * NHEADS];

    int p = blockIdx.x;
    int t = threadIdx.x;
    const float* qrow = g_q + (size_t)p * HID;
    const float* krow = g_k + (size_t)p * HID;
    const float* vrow = g_v + (size_t)p * HID;

    for (int c = t; c < HID; c += 256) {
        int n = c / DH;
        int j = c - n * DH;
        qt[j * NHEADS + n] = qrow[c];
        kt[j * NHEADS + n] = krow[c];
        vs[c] = vrow[c];
    }
    __syncthreads();

    {
        int m = t >> 4;
        int n = t & 15;
        float acc = 0.0f;
        #pragma unroll 8
        for (int j = 0; j < DH; j++)
            acc += qt[j * NHEADS + n] * kt[j * NHEADS + m];
        w[n * NHEADS + m] = acc * (1.0f / 12.0f);
    }
    __syncthreads();

    if (t < NHEADS) {
        float mx = -1e30f;
        #pragma unroll
        for (int m = 0; m < NHEADS; m++) mx = fmaxf(mx, w[t * NHEADS + m]);
        float sum = 0.0f;
        #pragma unroll
        for (int m = 0; m < NHEADS; m++) {
            float e = expf(w[t * NHEADS + m] - mx);
            w[t * NHEADS + m] = e;
            sum += e;
        }
        float inv = 1.0f / sum;
        #pragma unroll
        for (int m = 0; m < NHEADS; m++) w[t * NHEADS + m] *= inv;
    }
    __syncthreads();

    float* arow = g_attn + (size_t)p * HID;
    for (int c = t; c < HID; c += 256) {
        int n = c / DH;
        int j = c - n * DH;
        float acc = 0.0f;
        #pragma unroll
        for (int m = 0; m < NHEADS; m++)
            acc += w[n * NHEADS + m] * vs[m * DH + j];
        uint32_t u = __float_as_uint(acc);
        CVT_TF32(u);
        arow[c] = __uint_as_float(u);
    }
}

// ======================= residual + LayerNorm ==============================
__device__ __forceinline__ float block_sum(float v, float* red) {
    #pragma unroll
    for (int o = 16; o > 0; o >>= 1) v += __shfl_xor_sync(0xFFFFFFFFu, v, o);
    int warp = threadIdx.x >> 5, lane = threadIdx.x & 31;
    if (lane == 0) red[warp] = v;
    __syncthreads();
    if (warp == 0) {
        float x = (lane < 8) ? red[lane] : 0.0f;
        #pragma unroll
        for (int o = 4; o > 0; o >>= 1) x += __shfl_xor_sync(0xFFFFFFFFu, x, o);
        if (lane == 0) red[0] = x;
    }
    __syncthreads();
    float r = red[0];
    __syncthreads();
    return r;
}

__global__ __launch_bounds__(256)
void ln_kernel(const float* __restrict__ x, const float* __restrict__ bo,
               const float* __restrict__ gamma, const float* __restrict__ beta,
               float* __restrict__ out) {
    __shared__ float ybuf[HID];
    __shared__ float red[8];

    int row = blockIdx.x;
    int t = threadIdx.x;
    const float* xr = x + (size_t)row * HID;
    const float* orow = g_o + (size_t)row * HID;

    float s = 0.0f;
    for (int c = t; c < HID; c += 256) {
        float y = xr[c] + orow[c] + bo[c];
        ybuf[c] = y;
        s += y;
    }
    float total = block_sum(s, red);
    float mu = total * (1.0f / (float)HID);

    float vsum = 0.0f;
    for (int c = t; c < HID; c += 256) {
        float dy = ybuf[c] - mu;
        vsum += dy * dy;
    }
    float vtot = block_sum(vsum, red);
    float var = vtot * (1.0f / (float)HID);
    float rstd = rsqrtf(var + 1e-5f);

    float* orow_out = out + (size_t)row * HID;
    for (int c = t; c < HID; c += 256) {
        orow_out[c] = (ybuf[c] - mu) * rstd * gamma[c] + beta[c];
    }
}

// ---------------------------------------------------------------------------
extern "C" void kernel_launch(void* const* d_in, const int* in_sizes, int n_in,
                              void* d_out, int out_size) {
    const float* x  = (const float*)d_in[0];
    const float* wq = (const float*)d_in[1];
    const float* bq = (const float*)d_in[2];
    const float* wk = (const float*)d_in[3];
    const float* bk = (const float*)d_in[4];
    const float* wv = (const float*)d_in[5];
    const float* bv = (const float*)d_in[6];
    const float* wo = (const float*)d_in[7];
    const float* bo = (const float*)d_in[8];
    const float* g  = (const float*)d_in[9];
    const float* bl = (const float*)d_in[10];
    float* out = (float*)d_out;

    int M = in_sizes[0] / HID;   // b*s = 8192

    float *q, *k, *v, *attn, *o, *xr, *wqr, *wkr, *wvr, *wor;
    cudaGetSymbolAddress((void**)&q,    g_q);
    cudaGetSymbolAddress((void**)&k,    g_k);
    cudaGetSymbolAddress((void**)&v,    g_v);
    cudaGetSymbolAddress((void**)&attn, g_attn);
    cudaGetSymbolAddress((void**)&o,    g_o);
    cudaGetSymbolAddress((void**)&xr,   g_xr);
    cudaGetSymbolAddress((void**)&wqr,  g_wqr);
    cudaGetSymbolAddress((void**)&wkr,  g_wkr);
    cudaGetSymbolAddress((void**)&wvr,  g_wvr);
    cudaGetSymbolAddress((void**)&wor,  g_wor);

    static int smem_set = 0;
    if (!smem_set) {
        cudaFuncSetAttribute(gemm_tf32_kernel<0>,
                             cudaFuncAttributeMaxDynamicSharedMemorySize, GEMM_SMEM_BYTES);
        cudaFuncSetAttribute(gemm_tf32_kernel<1>,
                             cudaFuncAttributeMaxDynamicSharedMemorySize, GEMM_SMEM_BYTES);
        cudaFuncSetAttribute(gemm_tf32_kernel<2>,
                             cudaFuncAttributeMaxDynamicSharedMemorySize, GEMM_SMEM_BYTES);
        smem_set = 1;
    }

    build_omega_kernel<<<(HALF_D + 255) / 256, 256>>>();
    build_rope_kernel<<<(SLEN * HALF_D + 255) / 256, 256>>>();

    // pre-round inputs to tf32 precision (replaces in-loop cvt)
    {
        int nx4 = (M * HID) / 4;
        int nw4 = (HID * HID) / 4;
        round_tf32_kernel<<<(nx4 + 255) / 256, 256>>>(x,  xr,  nx4);
        round_tf32_kernel<<<(nw4 + 255) / 256, 256>>>(wq, wqr, nw4);
        round_tf32_kernel<<<(nw4 + 255) / 256, 256>>>(wk, wkr, nw4);
        round_tf32_kernel<<<(nw4 + 255) / 256, 256>>>(wv, wvr, nw4);
        round_tf32_kernel<<<(nw4 + 255) / 256, 256>>>(wo, wor, nw4);
    }

    dim3 ggrid(HID / BN, M / BM);   // 9 x 64
    gemm_tf32_kernel<2><<<ggrid, 256, GEMM_SMEM_BYTES>>>(xr, wqr, q, bq, M, HID, HID);
    gemm_tf32_kernel<2><<<ggrid, 256, GEMM_SMEM_BYTES>>>(xr, wkr, k, bk, M, HID, HID);
    gemm_tf32_kernel<1><<<ggrid, 256, GEMM_SMEM_BYTES>>>(xr, wvr, v, bv, M, HID, HID);

    attention_kernel<<<M, 256>>>(M);

    gemm_tf32_kernel<0><<<ggrid, 256, GEMM_SMEM_BYTES>>>(attn, wor, o, bo, M, HID, HID);

    ln_kernel<<<M, 256>>>(x, bo, g, bl, out);

    (void)n_in; (void)out_size;
}

// round 9
// speedup vs baseline: 5.5842x; 1.6447x over previous
#include <cuda_runtime.h>
#include <cuda_fp16.h>
#include <math.h>
#include <cstdint>

#define HID    2304
#define HALF_D 1152
#define NHEADS 16
#define DH     144
#define SLEN   2048
#define MMAX   8192

// -------- scratch (static device globals; no runtime allocation) ----------
__device__ float  g_q[(size_t)MMAX * HID];
__device__ float  g_k[(size_t)MMAX * HID];
__device__ float  g_v[(size_t)MMAX * HID];
__device__ float  g_o[(size_t)MMAX * HID];
__device__ __half g_xh[(size_t)MMAX * HID];      // fp16 x
__device__ __half g_attnh[(size_t)MMAX * HID];   // fp16 attention output
__device__ __half g_wqh[(size_t)HID * HID];      // fp16 weights
__device__ __half g_wkh[(size_t)HID * HID];
__device__ __half g_wvh[(size_t)HID * HID];
__device__ __half g_woh[(size_t)HID * HID];
__device__ float  g_cos[SLEN * HALF_D];
__device__ float  g_sin[SLEN * HALF_D];
__device__ double g_omega[HALF_D];

// ---------------------------------------------------------------------------
// RoPE tables.
// ---------------------------------------------------------------------------
__global__ void build_omega_kernel() {
    int i = blockIdx.x * blockDim.x + threadIdx.x;
    if (i < HALF_D) {
        double scale = (2.0 * (double)i) / (double)HID;
        g_omega[i] = exp(-scale * log(10000.0));
    }
}

__global__ void build_rope_kernel() {
    int idx = blockIdx.x * blockDim.x + threadIdx.x;
    if (idx >= SLEN * HALF_D) return;
    int pos = idx / HALF_D;
    int i   = idx - pos * HALF_D;
    double ang = (double)pos * g_omega[i];
    double n = floor(ang * 0.15915494309189535);
    double r = ang - n * 6.283185307179586476925286766559;
    float s, c;
    sincosf((float)r, &s, &c);
    g_cos[idx] = c;
    g_sin[idx] = s;
}

// ---------------------------------------------------------------------------
// f32 -> fp16 conversion (RNE), vectorized.
// ---------------------------------------------------------------------------
__global__ void to_half_kernel(const float* __restrict__ in,
                               __half* __restrict__ out, int n4) {
    int i = blockIdx.x * blockDim.x + threadIdx.x;
    if (i >= n4) return;
    float4 v = ((const float4*)in)[i];
    __half2 h0 = __floats2half2_rn(v.x, v.y);
    __half2 h1 = __floats2half2_rn(v.z, v.w);
    ((__half2*)out)[2 * i]     = h0;
    ((__half2*)out)[2 * i + 1] = h1;
}

// ---------------------------------------------------------------------------
// PTX helpers
// ---------------------------------------------------------------------------
__device__ __forceinline__ void cp_async16(uint32_t dst, const void* src) {
    asm volatile("cp.async.cg.shared.global [%0], [%1], 16;\n" :: "r"(dst), "l"(src));
}
__device__ __forceinline__ void cp_commit() {
    asm volatile("cp.async.commit_group;\n");
}
__device__ __forceinline__ void cp_wait1() {
    asm volatile("cp.async.wait_group 1;\n");
}

#define LDSM4(r0, r1, r2, r3, addr) \
    asm volatile("ldmatrix.sync.aligned.m8n8.x4.shared.b16 {%0,%1,%2,%3}, [%4];" \
                 : "=r"(r0), "=r"(r1), "=r"(r2), "=r"(r3) : "r"(addr))

#define MMA_F16(d, a0, a1, a2, a3, b0, b1) \
    asm volatile("mma.sync.aligned.m16n8k16.row.col.f32.f16.f16.f32 " \
                 "{%0,%1,%2,%3}, {%4,%5,%6,%7}, {%8,%9}, {%0,%1,%2,%3};" \
                 : "+f"((d)[0]), "+f"((d)[1]), "+f"((d)[2]), "+f"((d)[3]) \
                 : "r"(a0), "r"(a1), "r"(a2), "r"(a3), "r"(b0), "r"(b1))

// ---------------------------------------------------------------------------
// C[M,N] = A[M,K] @ B[N,K]^T via raw mma.sync f16 (f32 accum) + ldmatrix.
// A,B are fp16 (pre-converted, RNE). CTA tile 128x256, 64 halfs (128B) per
// stage-row, 3-stage cp.async pipeline, 8 warps (2x4), 64x64 per warp.
// MODE: 0 = direct store; 1 = +bias; 2 = +bias then RoPE (register epilogue).
// ---------------------------------------------------------------------------
#define BM 128
#define BN 256
#define BKH 64                              // K halfs per stage (128 bytes)
#define A_BYTES (BM * 128)                  // 16384
#define B_BYTES (BN * 128)                  // 32768
#define STAGE_BYTES (A_BYTES + B_BYTES)     // 49152
#define GEMM_SMEM_BYTES (3 * STAGE_BYTES)   // 147456

__device__ __forceinline__ void load_stage(const __half* __restrict__ A,
                                           const __half* __restrict__ B,
                                           int K, int bm, int bn, int k0,
                                           uint32_t stg, int tid) {
    #pragma unroll
    for (int i = 0; i < 4; i++) {              // A: 1024 chunks of 16B (8 halfs)
        int e = i * 256 + tid;
        int r = e >> 3;
        int cb = (e & 7) * 16;
        cp_async16(stg + r * 128 + (cb ^ ((r & 7) << 4)),
                   A + (size_t)(bm + r) * K + k0 + (e & 7) * 8);
    }
    #pragma unroll
    for (int i = 0; i < 8; i++) {              // B: 2048 chunks
        int e = i * 256 + tid;
        int r = e >> 3;
        int cb = (e & 7) * 16;
        cp_async16(stg + A_BYTES + r * 128 + (cb ^ ((r & 7) << 4)),
                   B + (size_t)(bn + r) * K + k0 + (e & 7) * 8);
    }
}

template <int MODE>
__global__ __launch_bounds__(256, 1)
void gemm_f16_kernel(const __half* __restrict__ A, const __half* __restrict__ B,
                     float* __restrict__ C, const float* __restrict__ bias,
                     int M, int N, int K) {
    extern __shared__ char smem[];
    uint32_t sbase;
    asm("{ .reg .u64 t; cvta.to.shared.u64 t, %1; cvt.u32.u64 %0, t; }"
        : "=r"(sbase) : "l"(smem));

    const int tid  = threadIdx.x;
    const int warp = tid >> 5;
    const int lane = tid & 31;
    const int bm = blockIdx.y * BM;
    const int bn = blockIdx.x * BN;
    const int wm = (warp >> 2) * 64;
    const int wn = (warp & 3) * 64;

    const int lr = lane & 7;           // row within 8-row ldmatrix tile
    const int lh = (lane >> 3) & 1;    // tile-pair selector
    const int lc = lane >> 4;          // tile-pair selector

    // A x4 tiles: (m0-7,kL),(m8-15,kL),(m0-7,kH),(m8-15,kH): row = +lh*8, chunk=lc
    // B x4 tiles: (n0-7,kL),(n0-7,kH),(n8-15,kL),(n8-15,kH): row = +lc*8, chunk=lh
    int rowA[4], rowB[4];
    #pragma unroll
    for (int mb = 0; mb < 4; mb++) rowA[mb] = wm + mb * 16 + lr + lh * 8;
    #pragma unroll
    for (int j = 0; j < 4; j++)    rowB[j] = wn + j * 16 + lr + lc * 8;

    float acc[4][8][4];
    #pragma unroll
    for (int mb = 0; mb < 4; mb++)
        #pragma unroll
        for (int nb = 0; nb < 8; nb++)
            #pragma unroll
            for (int e = 0; e < 4; e++) acc[mb][nb][e] = 0.0f;

    const int kIters = K / BKH;   // 36

    load_stage(A, B, K, bm, bn, 0, sbase, tid);
    cp_commit();
    load_stage(A, B, K, bm, bn, BKH, sbase + STAGE_BYTES, tid);
    cp_commit();

    int stage = 0;
    for (int kt = 0; kt < kIters; kt++) {
        cp_wait1();
        __syncthreads();

        int nk = kt + 2;
        if (nk < kIters)
            load_stage(A, B, K, bm, bn, nk * BKH,
                       sbase + (nk % 3) * STAGE_BYTES, tid);
        cp_commit();

        const uint32_t stg = sbase + stage * STAGE_BYTES;

        #pragma unroll
        for (int kk = 0; kk < 4; kk++) {       // 4 k16-steps per stage
            const int kbL = kk * 32;           // byte offset of k16-slab in row
            uint32_t a[4][4], b[4][4];
            #pragma unroll
            for (int mb = 0; mb < 4; mb++) {
                uint32_t ad = stg + rowA[mb] * 128 +
                              ((kbL + lc * 16) ^ ((rowA[mb] & 7) << 4));
                LDSM4(a[mb][0], a[mb][1], a[mb][2], a[mb][3], ad);
            }
            #pragma unroll
            for (int j = 0; j < 4; j++) {
                uint32_t bd = stg + A_BYTES + rowB[j] * 128 +
                              ((kbL + lh * 16) ^ ((rowB[j] & 7) << 4));
                LDSM4(b[j][0], b[j][1], b[j][2], b[j][3], bd);
            }
            #pragma unroll
            for (int mb = 0; mb < 4; mb++)
                #pragma unroll
                for (int j = 0; j < 4; j++) {
                    MMA_F16(acc[mb][2 * j],     a[mb][0], a[mb][1], a[mb][2], a[mb][3],
                            b[j][0], b[j][1]);
                    MMA_F16(acc[mb][2 * j + 1], a[mb][0], a[mb][1], a[mb][2], a[mb][3],
                            b[j][2], b[j][3]);
                }
        }

        stage = (stage + 1 == 3) ? 0 : stage + 1;
    }

    // -------- register epilogue: bias / RoPE, st.global.v2 ---------
    #pragma unroll
    for (int mb = 0; mb < 4; mb++) {
        const int r0 = bm + wm + mb * 16 + (lane >> 2);
        #pragma unroll
        for (int nb = 0; nb < 8; nb++) {
            const int gc = bn + wn + nb * 8 + (lane & 3) * 2;
            float x0 = acc[mb][nb][0], x1 = acc[mb][nb][1];
            float y0 = acc[mb][nb][2], y1 = acc[mb][nb][3];
            if (MODE >= 1) {
                float2 bb = *(const float2*)(bias + gc);
                x0 += bb.x; x1 += bb.y;
                y0 += bb.x; y1 += bb.y;
            }
            if (MODE == 2) {
                const int i = gc >> 1;
                const int p0 = r0 & (SLEN - 1);
                const int p1 = (r0 + 8) & (SLEN - 1);
                float c0 = g_cos[p0 * HALF_D + i], s0 = g_sin[p0 * HALF_D + i];
                float c1 = g_cos[p1 * HALF_D + i], s1 = g_sin[p1 * HALF_D + i];
                float t0 = c0 * x0 - s0 * x1;
                float t1 = s0 * x0 + c0 * x1;
                x0 = t0; x1 = t1;
                t0 = c1 * y0 - s1 * y1;
                t1 = s1 * y0 + c1 * y1;
                y0 = t0; y1 = t1;
            }
            *(float2*)(C + (size_t)r0 * N + gc)       = make_float2(x0, x1);
            *(float2*)(C + (size_t)(r0 + 8) * N + gc) = make_float2(y0, y1);
        }
    }
}

// ======================= head-mixing attention =============================
// Output is converted to fp16 at store (feeds the final GEMM).
__global__ __launch_bounds__(256)
void attention_kernel(int M) {
    __shared__ float qt[DH * NHEADS];
    __shared__ float kt[DH * NHEADS];
    __shared__ float vs[HID];
    __shared__ float w[NHEADS * NHEADS];

    int p = blockIdx.x;
    int t = threadIdx.x;
    const float* qrow = g_q + (size_t)p * HID;
    const float* krow = g_k + (size_t)p * HID;
    const float* vrow = g_v + (size_t)p * HID;

    for (int c = t; c < HID; c += 256) {
        int n = c / DH;
        int j = c - n * DH;
        qt[j * NHEADS + n] = qrow[c];
        kt[j * NHEADS + n] = krow[c];
        vs[c] = vrow[c];
    }
    __syncthreads();

    {
        int m = t >> 4;
        int n = t & 15;
        float acc = 0.0f;
        #pragma unroll 8
        for (int j = 0; j < DH; j++)
            acc += qt[j * NHEADS + n] * kt[j * NHEADS + m];
        w[n * NHEADS + m] = acc * (1.0f / 12.0f);
    }
    __syncthreads();

    if (t < NHEADS) {
        float mx = -1e30f;
        #pragma unroll
        for (int m = 0; m < NHEADS; m++) mx = fmaxf(mx, w[t * NHEADS + m]);
        float sum = 0.0f;
        #pragma unroll
        for (int m = 0; m < NHEADS; m++) {
            float e = expf(w[t * NHEADS + m] - mx);
            w[t * NHEADS + m] = e;
            sum += e;
        }
        float inv = 1.0f / sum;
        #pragma unroll
        for (int m = 0; m < NHEADS; m++) w[t * NHEADS + m] *= inv;
    }
    __syncthreads();

    __half* arow = g_attnh + (size_t)p * HID;
    for (int c = t; c < HID; c += 256) {
        int n = c / DH;
        int j = c - n * DH;
        float acc = 0.0f;
        #pragma unroll
        for (int m = 0; m < NHEADS; m++)
            acc += w[n * NHEADS + m] * vs[m * DH + j];
        arow[c] = __float2half_rn(acc);
    }
}

// ======================= residual + LayerNorm ==============================
__device__ __forceinline__ float block_sum(float v, float* red) {
    #pragma unroll
    for (int o = 16; o > 0; o >>= 1) v += __shfl_xor_sync(0xFFFFFFFFu, v, o);
    int warp = threadIdx.x >> 5, lane = threadIdx.x & 31;
    if (lane == 0) red[warp] = v;
    __syncthreads();
    if (warp == 0) {
        float x = (lane < 8) ? red[lane] : 0.0f;
        #pragma unroll
        for (int o = 4; o > 0; o >>= 1) x += __shfl_xor_sync(0xFFFFFFFFu, x, o);
        if (lane == 0) red[0] = x;
    }
    __syncthreads();
    float r = red[0];
    __syncthreads();
    return r;
}

__global__ __launch_bounds__(256)
void ln_kernel(const float* __restrict__ x, const float* __restrict__ bo,
               const float* __restrict__ gamma, const float* __restrict__ beta,
               float* __restrict__ out) {
    __shared__ float ybuf[HID];
    __shared__ float red[8];

    int row = blockIdx.x;
    int t = threadIdx.x;
    const float* xr = x + (size_t)row * HID;
    const float* orow = g_o + (size_t)row * HID;

    float s = 0.0f;
    for (int c = t; c < HID; c += 256) {
        float y = xr[c] + orow[c] + bo[c];
        ybuf[c] = y;
        s += y;
    }
    float total = block_sum(s, red);
    float mu = total * (1.0f / (float)HID);

    float vsum = 0.0f;
    for (int c = t; c < HID; c += 256) {
        float dy = ybuf[c] - mu;
        vsum += dy * dy;
    }
    float vtot = block_sum(vsum, red);
    float var = vtot * (1.0f / (float)HID);
    float rstd = rsqrtf(var + 1e-5f);

    float* orow_out = out + (size_t)row * HID;
    for (int c = t; c < HID; c += 256) {
        orow_out[c] = (ybuf[c] - mu) * rstd * gamma[c] + beta[c];
    }
}

// ---------------------------------------------------------------------------
extern "C" void kernel_launch(void* const* d_in, const int* in_sizes, int n_in,
                              void* d_out, int out_size) {
    const float* x  = (const float*)d_in[0];
    const float* wq = (const float*)d_in[1];
    const float* bq = (const float*)d_in[2];
    const float* wk = (const float*)d_in[3];
    const float* bk = (const float*)d_in[4];
    const float* wv = (const float*)d_in[5];
    const float* bv = (const float*)d_in[6];
    const float* wo = (const float*)d_in[7];
    const float* bo = (const float*)d_in[8];
    const float* g  = (const float*)d_in[9];
    const float* bl = (const float*)d_in[10];
    float* out = (float*)d_out;

    int M = in_sizes[0] / HID;   // b*s = 8192

    float *q, *k, *v, *o;
    __half *xh, *attnh, *wqh, *wkh, *wvh, *woh;
    cudaGetSymbolAddress((void**)&q,     g_q);
    cudaGetSymbolAddress((void**)&k,     g_k);
    cudaGetSymbolAddress((void**)&v,     g_v);
    cudaGetSymbolAddress((void**)&o,     g_o);
    cudaGetSymbolAddress((void**)&xh,    g_xh);
    cudaGetSymbolAddress((void**)&attnh, g_attnh);
    cudaGetSymbolAddress((void**)&wqh,   g_wqh);
    cudaGetSymbolAddress((void**)&wkh,   g_wkh);
    cudaGetSymbolAddress((void**)&wvh,   g_wvh);
    cudaGetSymbolAddress((void**)&woh,   g_woh);

    static int smem_set = 0;
    if (!smem_set) {
        cudaFuncSetAttribute(gemm_f16_kernel<0>,
                             cudaFuncAttributeMaxDynamicSharedMemorySize, GEMM_SMEM_BYTES);
        cudaFuncSetAttribute(gemm_f16_kernel<1>,
                             cudaFuncAttributeMaxDynamicSharedMemorySize, GEMM_SMEM_BYTES);
        cudaFuncSetAttribute(gemm_f16_kernel<2>,
                             cudaFuncAttributeMaxDynamicSharedMemorySize, GEMM_SMEM_BYTES);
        smem_set = 1;
    }

    build_omega_kernel<<<(HALF_D + 255) / 256, 256>>>();
    build_rope_kernel<<<(SLEN * HALF_D + 255) / 256, 256>>>();

    // convert inputs to fp16 (RNE; same mantissa precision as tf32-rna)
    {
        int nx4 = (M * HID) / 4;
        int nw4 = (HID * HID) / 4;
        to_half_kernel<<<(nx4 + 255) / 256, 256>>>(x,  xh,  nx4);
        to_half_kernel<<<(nw4 + 255) / 256, 256>>>(wq, wqh, nw4);
        to_half_kernel<<<(nw4 + 255) / 256, 256>>>(wk, wkh, nw4);
        to_half_kernel<<<(nw4 + 255) / 256, 256>>>(wv, wvh, nw4);
        to_half_kernel<<<(nw4 + 255) / 256, 256>>>(wo, woh, nw4);
    }

    dim3 ggrid(HID / BN, M / BM);   // 9 x 64
    gemm_f16_kernel<2><<<ggrid, 256, GEMM_SMEM_BYTES>>>(xh, wqh, q, bq, M, HID, HID);
    gemm_f16_kernel<2><<<ggrid, 256, GEMM_SMEM_BYTES>>>(xh, wkh, k, bk, M, HID, HID);
    gemm_f16_kernel<1><<<ggrid, 256, GEMM_SMEM_BYTES>>>(xh, wvh, v, bv, M, HID, HID);

    attention_kernel<<<M, 256>>>(M);

    gemm_f16_kernel<0><<<ggrid, 256, GEMM_SMEM_BYTES>>>(attnh, woh, o, bo, M, HID, HID);

    ln_kernel<<<M, 256>>>(x, bo, g, bl, out);

    (void)n_in; (void)out_size;
}

// round 10
// speedup vs baseline: 5.7155x; 1.0235x over previous
#include <cuda_runtime.h>
#include <cuda_fp16.h>
#include <math.h>
#include <cstdint>

#define HID    2304
#define HALF_D 1152
#define NHEADS 16
#define DH     144
#define SLEN   2048
#define MMAX   8192

// -------- scratch (static device globals; no runtime allocation) ----------
__device__ __half g_q16[(size_t)MMAX * HID];     // fp16 q (post-RoPE)
__device__ __half g_k16[(size_t)MMAX * HID];     // fp16 k (post-RoPE)
__device__ __half g_v16[(size_t)MMAX * HID];     // fp16 v (post-bias)
__device__ float  g_o[(size_t)MMAX * HID];       // f32 wo-GEMM output
__device__ __half g_xh[(size_t)MMAX * HID];      // fp16 x
__device__ __half g_attnh[(size_t)MMAX * HID];   // fp16 attention output
__device__ __half g_wqh[(size_t)HID * HID];      // fp16 weights
__device__ __half g_wkh[(size_t)HID * HID];
__device__ __half g_wvh[(size_t)HID * HID];
__device__ __half g_woh[(size_t)HID * HID];
__device__ float  g_cos[SLEN * HALF_D];
__device__ float  g_sin[SLEN * HALF_D];
__device__ double g_omega[HALF_D];

// ---------------------------------------------------------------------------
// RoPE tables.
// ---------------------------------------------------------------------------
__global__ void build_omega_kernel() {
    int i = blockIdx.x * blockDim.x + threadIdx.x;
    if (i < HALF_D) {
        double scale = (2.0 * (double)i) / (double)HID;
        g_omega[i] = exp(-scale * log(10000.0));
    }
}

__global__ void build_rope_kernel() {
    int idx = blockIdx.x * blockDim.x + threadIdx.x;
    if (idx >= SLEN * HALF_D) return;
    int pos = idx / HALF_D;
    int i   = idx - pos * HALF_D;
    double ang = (double)pos * g_omega[i];
    double n = floor(ang * 0.15915494309189535);
    double r = ang - n * 6.283185307179586476925286766559;
    float s, c;
    sincosf((float)r, &s, &c);
    g_cos[idx] = c;
    g_sin[idx] = s;
}

// ---------------------------------------------------------------------------
// f32 -> fp16 conversion (RNE), vectorized.
// ---------------------------------------------------------------------------
__global__ void to_half_kernel(const float* __restrict__ in,
                               __half* __restrict__ out, int n4) {
    int i = blockIdx.x * blockDim.x + threadIdx.x;
    if (i >= n4) return;
    float4 v = ((const float4*)in)[i];
    ((__half2*)out)[2 * i]     = __floats2half2_rn(v.x, v.y);
    ((__half2*)out)[2 * i + 1] = __floats2half2_rn(v.z, v.w);
}

// ---------------------------------------------------------------------------
// PTX helpers
// ---------------------------------------------------------------------------
__device__ __forceinline__ void cp_async16(uint32_t dst, const void* src) {
    asm volatile("cp.async.cg.shared.global [%0], [%1], 16;\n" :: "r"(dst), "l"(src));
}
__device__ __forceinline__ void cp_commit() {
    asm volatile("cp.async.commit_group;\n");
}
__device__ __forceinline__ void cp_wait1() {
    asm volatile("cp.async.wait_group 1;\n");
}

#define LDSM4(r0, r1, r2, r3, addr) \
    asm volatile("ldmatrix.sync.aligned.m8n8.x4.shared.b16 {%0,%1,%2,%3}, [%4];" \
                 : "=r"(r0), "=r"(r1), "=r"(r2), "=r"(r3) : "r"(addr))

#define MMA_F16(d, a0, a1, a2, a3, b0, b1) \
    asm volatile("mma.sync.aligned.m16n8k16.row.col.f32.f16.f16.f32 " \
                 "{%0,%1,%2,%3}, {%4,%5,%6,%7}, {%8,%9}, {%0,%1,%2,%3};" \
                 : "+f"((d)[0]), "+f"((d)[1]), "+f"((d)[2]), "+f"((d)[3]) \
                 : "r"(a0), "r"(a1), "r"(a2), "r"(a3), "r"(b0), "r"(b1))

// ---------------------------------------------------------------------------
// C[M,N] = A[M,K] @ B[N,K]^T via raw mma.sync f16 (f32 accum) + ldmatrix.
// CTA tile 128x128, 128 threads (4 warps, 64x64 each), 2 CTAs/SM,
// 3-stage cp.async pipeline. Independent CTA barriers decouple stage syncs.
// MODE: 0 = direct f32 store; 1 = +bias fp16 store; 2 = +bias,RoPE fp16 store.
// ---------------------------------------------------------------------------
#define BM 128
#define BN 128
#define BKH 64                              // K halfs per stage (128 bytes)
#define A_BYTES (BM * 128)                  // 16384
#define B_BYTES (BN * 128)                  // 16384
#define STAGE_BYTES (A_BYTES + B_BYTES)     // 32768
#define GEMM_SMEM_BYTES (3 * STAGE_BYTES)   // 98304 per CTA (x2 CTA = 192K)

__device__ __forceinline__ void load_stage(const __half* __restrict__ A,
                                           const __half* __restrict__ B,
                                           int K, int bm, int bn, int k0,
                                           uint32_t stg, int tid) {
    #pragma unroll
    for (int i = 0; i < 8; i++) {              // A: 1024 chunks of 16B
        int e = i * 128 + tid;
        int r = e >> 3;
        int cb = (e & 7) * 16;
        cp_async16(stg + r * 128 + (cb ^ ((r & 7) << 4)),
                   A + (size_t)(bm + r) * K + k0 + (e & 7) * 8);
    }
    #pragma unroll
    for (int i = 0; i < 8; i++) {              // B: 1024 chunks
        int e = i * 128 + tid;
        int r = e >> 3;
        int cb = (e & 7) * 16;
        cp_async16(stg + A_BYTES + r * 128 + (cb ^ ((r & 7) << 4)),
                   B + (size_t)(bn + r) * K + k0 + (e & 7) * 8);
    }
}

template <int MODE>
__global__ __launch_bounds__(128, 2)
void gemm_f16_kernel(const __half* __restrict__ A, const __half* __restrict__ B,
                     void* __restrict__ Cv, const float* __restrict__ bias,
                     int M, int N, int K) {
    extern __shared__ char smem[];
    uint32_t sbase;
    asm("{ .reg .u64 t; cvta.to.shared.u64 t, %1; cvt.u32.u64 %0, t; }"
        : "=r"(sbase) : "l"(smem));

    const int tid  = threadIdx.x;
    const int warp = tid >> 5;
    const int lane = tid & 31;
    const int bm = blockIdx.y * BM;
    const int bn = blockIdx.x * BN;
    const int wm = (warp >> 1) * 64;   // 2 warps along M
    const int wn = (warp & 1) * 64;    // 2 warps along N

    const int lr = lane & 7;
    const int lh = (lane >> 3) & 1;
    const int lc = lane >> 4;

    int rowA[4], rowB[4];
    #pragma unroll
    for (int mb = 0; mb < 4; mb++) rowA[mb] = wm + mb * 16 + lr + lh * 8;
    #pragma unroll
    for (int j = 0; j < 4; j++)    rowB[j] = wn + j * 16 + lr + lc * 8;

    float acc[4][8][4];
    #pragma unroll
    for (int mb = 0; mb < 4; mb++)
        #pragma unroll
        for (int nb = 0; nb < 8; nb++)
            #pragma unroll
            for (int e = 0; e < 4; e++) acc[mb][nb][e] = 0.0f;

    const int kIters = K / BKH;   // 36

    load_stage(A, B, K, bm, bn, 0, sbase, tid);
    cp_commit();
    load_stage(A, B, K, bm, bn, BKH, sbase + STAGE_BYTES, tid);
    cp_commit();

    int stage = 0;
    for (int kt = 0; kt < kIters; kt++) {
        cp_wait1();
        __syncthreads();

        int nk = kt + 2;
        if (nk < kIters)
            load_stage(A, B, K, bm, bn, nk * BKH,
                       sbase + (nk % 3) * STAGE_BYTES, tid);
        cp_commit();

        const uint32_t stg = sbase + stage * STAGE_BYTES;

        #pragma unroll
        for (int kk = 0; kk < 4; kk++) {
            const int kbL = kk * 32;
            uint32_t a[4][4], b[4][4];
            #pragma unroll
            for (int mb = 0; mb < 4; mb++) {
                uint32_t ad = stg + rowA[mb] * 128 +
                              ((kbL + lc * 16) ^ ((rowA[mb] & 7) << 4));
                LDSM4(a[mb][0], a[mb][1], a[mb][2], a[mb][3], ad);
            }
            #pragma unroll
            for (int j = 0; j < 4; j++) {
                uint32_t bd = stg + A_BYTES + rowB[j] * 128 +
                              ((kbL + lh * 16) ^ ((rowB[j] & 7) << 4));
                LDSM4(b[j][0], b[j][1], b[j][2], b[j][3], bd);
            }
            #pragma unroll
            for (int mb = 0; mb < 4; mb++)
                #pragma unroll
                for (int j = 0; j < 4; j++) {
                    MMA_F16(acc[mb][2 * j],     a[mb][0], a[mb][1], a[mb][2], a[mb][3],
                            b[j][0], b[j][1]);
                    MMA_F16(acc[mb][2 * j + 1], a[mb][0], a[mb][1], a[mb][2], a[mb][3],
                            b[j][2], b[j][3]);
                }
        }

        stage = (stage + 1 == 3) ? 0 : stage + 1;
    }

    // -------- register epilogue ---------
    #pragma unroll
    for (int mb = 0; mb < 4; mb++) {
        const int r0 = bm + wm + mb * 16 + (lane >> 2);
        #pragma unroll
        for (int nb = 0; nb < 8; nb++) {
            const int gc = bn + wn + nb * 8 + (lane & 3) * 2;
            float x0 = acc[mb][nb][0], x1 = acc[mb][nb][1];
            float y0 = acc[mb][nb][2], y1 = acc[mb][nb][3];
            if (MODE == 0) {
                float* Cf = (float*)Cv;
                *(float2*)(Cf + (size_t)r0 * N + gc)       = make_float2(x0, x1);
                *(float2*)(Cf + (size_t)(r0 + 8) * N + gc) = make_float2(y0, y1);
            } else {
                float2 bb = *(const float2*)(bias + gc);
                x0 += bb.x; x1 += bb.y;
                y0 += bb.x; y1 += bb.y;
                if (MODE == 2) {
                    const int i = gc >> 1;
                    const int p0 = r0 & (SLEN - 1);
                    const int p1 = (r0 + 8) & (SLEN - 1);
                    float c0 = g_cos[p0 * HALF_D + i], s0 = g_sin[p0 * HALF_D + i];
                    float c1 = g_cos[p1 * HALF_D + i], s1 = g_sin[p1 * HALF_D + i];
                    float t0 = c0 * x0 - s0 * x1;
                    float t1 = s0 * x0 + c0 * x1;
                    x0 = t0; x1 = t1;
                    t0 = c1 * y0 - s1 * y1;
                    t1 = s1 * y0 + c1 * y1;
                    y0 = t0; y1 = t1;
                }
                __half* Ch = (__half*)Cv;
                *(__half2*)(Ch + (size_t)r0 * N + gc)       = __floats2half2_rn(x0, x1);
                *(__half2*)(Ch + (size_t)(r0 + 8) * N + gc) = __floats2half2_rn(y0, y1);
            }
        }
    }
}

// ======================= head-mixing attention =============================
// fp16 inputs (half2 loads), f32 math, fp16 output.
__global__ __launch_bounds__(256)
void attention_kernel(int M) {
    __shared__ float qt[DH * NHEADS];
    __shared__ float kt[DH * NHEADS];
    __shared__ float vs[HID];
    __shared__ float w[NHEADS * NHEADS];

    int p = blockIdx.x;
    int t = threadIdx.x;
    const __half2* qrow = (const __half2*)(g_q16 + (size_t)p * HID);
    const __half2* krow = (const __half2*)(g_k16 + (size_t)p * HID);
    const __half2* vrow = (const __half2*)(g_v16 + (size_t)p * HID);

    for (int c2 = t; c2 < HID / 2; c2 += 256) {
        int c = 2 * c2;
        int n = c / DH;
        int j = c - n * DH;          // even; j and j+1 share head n (DH even)
        float2 qf = __half22float2(qrow[c2]);
        float2 kf = __half22float2(krow[c2]);
        float2 vf = __half22float2(vrow[c2]);
        qt[j * NHEADS + n] = qf.x;
        qt[(j + 1) * NHEADS + n] = qf.y;
        kt[j * NHEADS + n] = kf.x;
        kt[(j + 1) * NHEADS + n] = kf.y;
        vs[c] = vf.x;
        vs[c + 1] = vf.y;
    }
    __syncthreads();

    {
        int m = t >> 4;
        int n = t & 15;
        float acc = 0.0f;
        #pragma unroll 8
        for (int j = 0; j < DH; j++)
            acc += qt[j * NHEADS + n] * kt[j * NHEADS + m];
        w[n * NHEADS + m] = acc * (1.0f / 12.0f);
    }
    __syncthreads();

    if (t < NHEADS) {
        float mx = -1e30f;
        #pragma unroll
        for (int m = 0; m < NHEADS; m++) mx = fmaxf(mx, w[t * NHEADS + m]);
        float sum = 0.0f;
        #pragma unroll
        for (int m = 0; m < NHEADS; m++) {
            float e = expf(w[t * NHEADS + m] - mx);
            w[t * NHEADS + m] = e;
            sum += e;
        }
        float inv = 1.0f / sum;
        #pragma unroll
        for (int m = 0; m < NHEADS; m++) w[t * NHEADS + m] *= inv;
    }
    __syncthreads();

    __half* arow = g_attnh + (size_t)p * HID;
    for (int c = t; c < HID; c += 256) {
        int n = c / DH;
        int j = c - n * DH;
        float acc = 0.0f;
        #pragma unroll
        for (int m = 0; m < NHEADS; m++)
            acc += w[n * NHEADS + m] * vs[m * DH + j];
        arow[c] = __float2half_rn(acc);
    }
}

// ======================= residual + LayerNorm ==============================
__device__ __forceinline__ float block_sum(float v, float* red) {
    #pragma unroll
    for (int o = 16; o > 0; o >>= 1) v += __shfl_xor_sync(0xFFFFFFFFu, v, o);
    int warp = threadIdx.x >> 5, lane = threadIdx.x & 31;
    if (lane == 0) red[warp] = v;
    __syncthreads();
    if (warp == 0) {
        float x = (lane < 8) ? red[lane] : 0.0f;
        #pragma unroll
        for (int o = 4; o > 0; o >>= 1) x += __shfl_xor_sync(0xFFFFFFFFu, x, o);
        if (lane == 0) red[0] = x;
    }
    __syncthreads();
    float r = red[0];
    __syncthreads();
    return r;
}

__global__ __launch_bounds__(256)
void ln_kernel(const float* __restrict__ x, const float* __restrict__ bo,
               const float* __restrict__ gamma, const float* __restrict__ beta,
               float* __restrict__ out) {
    __shared__ float ybuf[HID];
    __shared__ float red[8];

    int row = blockIdx.x;
    int t = threadIdx.x;
    const float* xr = x + (size_t)row * HID;
    const float* orow = g_o + (size_t)row * HID;

    float s = 0.0f;
    for (int c = t; c < HID; c += 256) {
        float y = xr[c] + orow[c] + bo[c];
        ybuf[c] = y;
        s += y;
    }
    float total = block_sum(s, red);
    float mu = total * (1.0f / (float)HID);

    float vsum = 0.0f;
    for (int c = t; c < HID; c += 256) {
        float dy = ybuf[c] - mu;
        vsum += dy * dy;
    }
    float vtot = block_sum(vsum, red);
    float var = vtot * (1.0f / (float)HID);
    float rstd = rsqrtf(var + 1e-5f);

    float* orow_out = out + (size_t)row * HID;
    for (int c = t; c < HID; c += 256) {
        orow_out[c] = (ybuf[c] - mu) * rstd * gamma[c] + beta[c];
    }
}

// ---------------------------------------------------------------------------
extern "C" void kernel_launch(void* const* d_in, const int* in_sizes, int n_in,
                              void* d_out, int out_size) {
    const float* x  = (const float*)d_in[0];
    const float* wq = (const float*)d_in[1];
    const float* bq = (const float*)d_in[2];
    const float* wk = (const float*)d_in[3];
    const float* bk = (const float*)d_in[4];
    const float* wv = (const float*)d_in[5];
    const float* bv = (const float*)d_in[6];
    const float* wo = (const float*)d_in[7];
    const float* bo = (const float*)d_in[8];
    const float* g  = (const float*)d_in[9];
    const float* bl = (const float*)d_in[10];
    float* out = (float*)d_out;

    int M = in_sizes[0] / HID;   // b*s = 8192

    float* o;
    __half *q16, *k16, *v16, *xh, *attnh, *wqh, *wkh, *wvh, *woh;
    cudaGetSymbolAddress((void**)&o,     g_o);
    cudaGetSymbolAddress((void**)&q16,   g_q16);
    cudaGetSymbolAddress((void**)&k16,   g_k16);
    cudaGetSymbolAddress((void**)&v16,   g_v16);
    cudaGetSymbolAddress((void**)&xh,    g_xh);
    cudaGetSymbolAddress((void**)&attnh, g_attnh);
    cudaGetSymbolAddress((void**)&wqh,   g_wqh);
    cudaGetSymbolAddress((void**)&wkh,   g_wkh);
    cudaGetSymbolAddress((void**)&wvh,   g_wvh);
    cudaGetSymbolAddress((void**)&woh,   g_woh);

    static int smem_set = 0;
    if (!smem_set) {
        cudaFuncSetAttribute(gemm_f16_kernel<0>,
                             cudaFuncAttributeMaxDynamicSharedMemorySize, GEMM_SMEM_BYTES);
        cudaFuncSetAttribute(gemm_f16_kernel<1>,
                             cudaFuncAttributeMaxDynamicSharedMemorySize, GEMM_SMEM_BYTES);
        cudaFuncSetAttribute(gemm_f16_kernel<2>,
                             cudaFuncAttributeMaxDynamicSharedMemorySize, GEMM_SMEM_BYTES);
        smem_set = 1;
    }

    build_omega_kernel<<<(HALF_D + 255) / 256, 256>>>();
    build_rope_kernel<<<(SLEN * HALF_D + 255) / 256, 256>>>();

    // convert inputs to fp16 (RNE)
    {
        int nx4 = (M * HID) / 4;
        int nw4 = (HID * HID) / 4;
        to_half_kernel<<<(nx4 + 255) / 256, 256>>>(x,  xh,  nx4);
        to_half_kernel<<<(nw4 + 255) / 256, 256>>>(wq, wqh, nw4);
        to_half_kernel<<<(nw4 + 255) / 256, 256>>>(wk, wkh, nw4);
        to_half_kernel<<<(nw4 + 255) / 256, 256>>>(wv, wvh, nw4);
        to_half_kernel<<<(nw4 + 255) / 256, 256>>>(wo, woh, nw4);
    }

    dim3 ggrid(HID / BN, M / BM);   // 18 x 64
    gemm_f16_kernel<2><<<ggrid, 128, GEMM_SMEM_BYTES>>>(xh, wqh, q16, bq, M, HID, HID);
    gemm_f16_kernel<2><<<ggrid, 128, GEMM_SMEM_BYTES>>>(xh, wkh, k16, bk, M, HID, HID);
    gemm_f16_kernel<1><<<ggrid, 128, GEMM_SMEM_BYTES>>>(xh, wvh, v16, bv, M, HID, HID);

    attention_kernel<<<M, 256>>>(M);

    gemm_f16_kernel<0><<<ggrid, 128, GEMM_SMEM_BYTES>>>(attnh, woh, o, bo, M, HID, HID);

    ln_kernel<<<M, 256>>>(x, bo, g, bl, out);

    (void)n_in; (void)out_size;
}

// round 11
// speedup vs baseline: 5.8626x; 1.0257x over previous
#include <cuda_runtime.h>
#include <cuda_fp16.h>
#include <math.h>
#include <cstdint>

#define HID    2304
#define HALF_D 1152
#define NHEADS 16
#define DH     144
#define SLEN   2048
#define MMAX   8192

// -------- scratch (static device globals; no runtime allocation) ----------
__device__ __half g_q16[(size_t)MMAX * HID];
__device__ __half g_k16[(size_t)MMAX * HID];
__device__ __half g_v16[(size_t)MMAX * HID];
__device__ float  g_o[(size_t)MMAX * HID];
__device__ __half g_xh[(size_t)MMAX * HID];
__device__ __half g_attnh[(size_t)MMAX * HID];
__device__ __half g_wqkvh[(size_t)3 * HID * HID];   // packed [3*HID, HID]
__device__ __half g_woh[(size_t)HID * HID];
__device__ float  g_cos[SLEN * HALF_D];
__device__ float  g_sin[SLEN * HALF_D];
__device__ double g_omega[HALF_D];

// ---------------------------------------------------------------------------
// RoPE tables.
// ---------------------------------------------------------------------------
__global__ void build_omega_kernel() {
    int i = blockIdx.x * blockDim.x + threadIdx.x;
    if (i < HALF_D) {
        double scale = (2.0 * (double)i) / (double)HID;
        g_omega[i] = exp(-scale * log(10000.0));
    }
}

__global__ void build_rope_kernel() {
    int idx = blockIdx.x * blockDim.x + threadIdx.x;
    if (idx >= SLEN * HALF_D) return;
    int pos = idx / HALF_D;
    int i   = idx - pos * HALF_D;
    double ang = (double)pos * g_omega[i];
    double n = floor(ang * 0.15915494309189535);
    double r = ang - n * 6.283185307179586476925286766559;
    float s, c;
    sincosf((float)r, &s, &c);
    g_cos[idx] = c;
    g_sin[idx] = s;
}

// ---------------------------------------------------------------------------
// f32 -> fp16 conversion (RNE), vectorized.
// ---------------------------------------------------------------------------
__global__ void to_half_kernel(const float* __restrict__ in,
                               __half* __restrict__ out, int n4) {
    int i = blockIdx.x * blockDim.x + threadIdx.x;
    if (i >= n4) return;
    float4 v = ((const float4*)in)[i];
    ((__half2*)out)[2 * i]     = __floats2half2_rn(v.x, v.y);
    ((__half2*)out)[2 * i + 1] = __floats2half2_rn(v.z, v.w);
}

// ---------------------------------------------------------------------------
// PTX helpers
// ---------------------------------------------------------------------------
__device__ __forceinline__ void cp_async16(uint32_t dst, const void* src) {
    asm volatile("cp.async.cg.shared.global [%0], [%1], 16;\n" :: "r"(dst), "l"(src));
}
__device__ __forceinline__ void cp_commit() {
    asm volatile("cp.async.commit_group;\n");
}
__device__ __forceinline__ void cp_wait1() {
    asm volatile("cp.async.wait_group 1;\n");
}

#define LDSM4(r0, r1, r2, r3, addr) \
    asm volatile("ldmatrix.sync.aligned.m8n8.x4.shared.b16 {%0,%1,%2,%3}, [%4];" \
                 : "=r"(r0), "=r"(r1), "=r"(r2), "=r"(r3) : "r"(addr))

#define MMA_F16(d, a0, a1, a2, a3, b0, b1) \
    asm volatile("mma.sync.aligned.m16n8k16.row.col.f32.f16.f16.f32 " \
                 "{%0,%1,%2,%3}, {%4,%5,%6,%7}, {%8,%9}, {%0,%1,%2,%3};" \
                 : "+f"((d)[0]), "+f"((d)[1]), "+f"((d)[2]), "+f"((d)[3]) \
                 : "r"(a0), "r"(a1), "r"(a2), "r"(a3), "r"(b0), "r"(b1))

// ---------------------------------------------------------------------------
// GEMM core: CTA tile 128x128, 128 threads (4 warps, 64x64), 2 CTAs/SM,
// 3-stage cp.async pipeline + LDSM double-buffering across k16-steps.
// ---------------------------------------------------------------------------
#define BM 128
#define BN 128
#define BKH 64                              // K halfs per stage (128 bytes)
#define A_BYTES (BM * 128)
#define B_BYTES (BN * 128)
#define STAGE_BYTES (A_BYTES + B_BYTES)     // 32768
#define GEMM_SMEM_BYTES (3 * STAGE_BYTES)   // 98304 per CTA

__device__ __forceinline__ void load_stage(const __half* __restrict__ A,
                                           const __half* __restrict__ B,
                                           int K, int bm, int bn, int k0,
                                           uint32_t stg, int tid) {
    #pragma unroll
    for (int i = 0; i < 8; i++) {
        int e = i * 128 + tid;
        int r = e >> 3;
        int cb = (e & 7) * 16;
        cp_async16(stg + r * 128 + (cb ^ ((r & 7) << 4)),
                   A + (size_t)(bm + r) * K + k0 + (e & 7) * 8);
    }
    #pragma unroll
    for (int i = 0; i < 8; i++) {
        int e = i * 128 + tid;
        int r = e >> 3;
        int cb = (e & 7) * 16;
        cp_async16(stg + A_BYTES + r * 128 + (cb ^ ((r & 7) << 4)),
                   B + (size_t)(bn + r) * K + k0 + (e & 7) * 8);
    }
}

struct Frag { uint32_t a[4][4]; uint32_t b[4][4]; };

__device__ __forceinline__ void ldsm_all(Frag& f, uint32_t stg, int kk,
                                         const int* rowA, const int* rowB,
                                         int lh, int lc) {
    const int kbL = kk * 32;
    #pragma unroll
    for (int mb = 0; mb < 4; mb++) {
        uint32_t ad = stg + rowA[mb] * 128 +
                      ((kbL + lc * 16) ^ ((rowA[mb] & 7) << 4));
        LDSM4(f.a[mb][0], f.a[mb][1], f.a[mb][2], f.a[mb][3], ad);
    }
    #pragma unroll
    for (int j = 0; j < 4; j++) {
        uint32_t bd = stg + A_BYTES + rowB[j] * 128 +
                      ((kbL + lh * 16) ^ ((rowB[j] & 7) << 4));
        LDSM4(f.b[j][0], f.b[j][1], f.b[j][2], f.b[j][3], bd);
    }
}

__device__ __forceinline__ void mma_all(float acc[4][8][4], const Frag& f) {
    #pragma unroll
    for (int mb = 0; mb < 4; mb++)
        #pragma unroll
        for (int j = 0; j < 4; j++) {
            MMA_F16(acc[mb][2 * j],     f.a[mb][0], f.a[mb][1], f.a[mb][2], f.a[mb][3],
                    f.b[j][0], f.b[j][1]);
            MMA_F16(acc[mb][2 * j + 1], f.a[mb][0], f.a[mb][1], f.a[mb][2], f.a[mb][3],
                    f.b[j][2], f.b[j][3]);
        }
}

__device__ __forceinline__ void gemm_mainloop(const __half* A, const __half* B,
                                              int K, int bm, int bn,
                                              uint32_t sbase, int tid,
                                              const int* rowA, const int* rowB,
                                              int lh, int lc,
                                              float acc[4][8][4]) {
    const int kIters = K / BKH;   // 36

    load_stage(A, B, K, bm, bn, 0, sbase, tid);
    cp_commit();
    load_stage(A, B, K, bm, bn, BKH, sbase + STAGE_BYTES, tid);
    cp_commit();

    int stage = 0;
    for (int kt = 0; kt < kIters; kt++) {
        cp_wait1();
        __syncthreads();

        int nk = kt + 2;
        if (nk < kIters)
            load_stage(A, B, K, bm, bn, nk * BKH,
                       sbase + (nk % 3) * STAGE_BYTES, tid);
        cp_commit();

        const uint32_t stg = sbase + stage * STAGE_BYTES;

        Frag f[2];
        ldsm_all(f[0], stg, 0, rowA, rowB, lh, lc);
        #pragma unroll
        for (int kk = 0; kk < 4; kk++) {
            int cur = kk & 1;
            if (kk < 3) ldsm_all(f[cur ^ 1], stg, kk + 1, rowA, rowB, lh, lc);
            mma_all(acc, f[cur]);
        }

        stage = (stage + 1 == 3) ? 0 : stage + 1;
    }
}

// ---------------------------------------------------------------------------
// Fused q/k/v projection: B is packed [3*HID, HID]; per-CTA sel picks the
// output (q/k: bias+RoPE, v: bias) — all fp16 stores.
// ---------------------------------------------------------------------------
__global__ __launch_bounds__(128, 2)
void gemm_qkv_kernel(const __half* __restrict__ A, const __half* __restrict__ B,
                     const float* __restrict__ bq, const float* __restrict__ bk,
                     const float* __restrict__ bv, int M, int K) {
    extern __shared__ char smem[];
    uint32_t sbase;
    asm("{ .reg .u64 t; cvta.to.shared.u64 t, %1; cvt.u32.u64 %0, t; }"
        : "=r"(sbase) : "l"(smem));

    const int tid  = threadIdx.x;
    const int warp = tid >> 5;
    const int lane = tid & 31;
    const int bm = blockIdx.y * BM;
    const int bn = blockIdx.x * BN;          // 0..6784
    const int wm = (warp >> 1) * 64;
    const int wn = (warp & 1) * 64;

    const int lr = lane & 7;
    const int lh = (lane >> 3) & 1;
    const int lc = lane >> 4;

    int rowA[4], rowB[4];
    #pragma unroll
    for (int mb = 0; mb < 4; mb++) rowA[mb] = wm + mb * 16 + lr + lh * 8;
    #pragma unroll
    for (int j = 0; j < 4; j++)    rowB[j] = wn + j * 16 + lr + lc * 8;

    float acc[4][8][4];
    #pragma unroll
    for (int mb = 0; mb < 4; mb++)
        #pragma unroll
        for (int nb = 0; nb < 8; nb++)
            #pragma unroll
            for (int e = 0; e < 4; e++) acc[mb][nb][e] = 0.0f;

    gemm_mainloop(A, B, K, bm, bn, sbase, tid, rowA, rowB, lh, lc, acc);

    // ---- epilogue: per-CTA uniform output selection ----
    const int sel   = bn / HID;              // 0=q, 1=k, 2=v
    const int cbase = bn - sel * HID;        // column offset within output
    const float* bias = (sel == 0) ? bq : (sel == 1) ? bk : bv;
    __half* Ch = (sel == 0) ? g_q16 : (sel == 1) ? g_k16 : g_v16;

    #pragma unroll
    for (int mb = 0; mb < 4; mb++) {
        const int r0 = bm + wm + mb * 16 + (lane >> 2);
        #pragma unroll
        for (int nb = 0; nb < 8; nb++) {
            const int lcol = cbase + wn + nb * 8 + (lane & 3) * 2;
            float x0 = acc[mb][nb][0], x1 = acc[mb][nb][1];
            float y0 = acc[mb][nb][2], y1 = acc[mb][nb][3];
            float2 bb = *(const float2*)(bias + lcol);
            x0 += bb.x; x1 += bb.y;
            y0 += bb.x; y1 += bb.y;
            if (sel < 2) {   // RoPE for q, k
                const int i = lcol >> 1;
                const int p0 = r0 & (SLEN - 1);
                const int p1 = (r0 + 8) & (SLEN - 1);
                float c0 = g_cos[p0 * HALF_D + i], s0 = g_sin[p0 * HALF_D + i];
                float c1 = g_cos[p1 * HALF_D + i], s1 = g_sin[p1 * HALF_D + i];
                float t0 = c0 * x0 - s0 * x1;
                float t1 = s0 * x0 + c0 * x1;
                x0 = t0; x1 = t1;
                t0 = c1 * y0 - s1 * y1;
                t1 = s1 * y0 + c1 * y1;
                y0 = t0; y1 = t1;
            }
            *(__half2*)(Ch + (size_t)r0 * HID + lcol)       = __floats2half2_rn(x0, x1);
            *(__half2*)(Ch + (size_t)(r0 + 8) * HID + lcol) = __floats2half2_rn(y0, y1);
        }
    }
}

// ---------------------------------------------------------------------------
// Output projection GEMM: plain f32 store (bias folded into LN kernel input).
// ---------------------------------------------------------------------------
__global__ __launch_bounds__(128, 2)
void gemm_wo_kernel(const __half* __restrict__ A, const __half* __restrict__ B,
                    float* __restrict__ C, int M, int N, int K) {
    extern __shared__ char smem[];
    uint32_t sbase;
    asm("{ .reg .u64 t; cvta.to.shared.u64 t, %1; cvt.u32.u64 %0, t; }"
        : "=r"(sbase) : "l"(smem));

    const int tid  = threadIdx.x;
    const int warp = tid >> 5;
    const int lane = tid & 31;
    const int bm = blockIdx.y * BM;
    const int bn = blockIdx.x * BN;
    const int wm = (warp >> 1) * 64;
    const int wn = (warp & 1) * 64;

    const int lr = lane & 7;
    const int lh = (lane >> 3) & 1;
    const int lc = lane >> 4;

    int rowA[4], rowB[4];
    #pragma unroll
    for (int mb = 0; mb < 4; mb++) rowA[mb] = wm + mb * 16 + lr + lh * 8;
    #pragma unroll
    for (int j = 0; j < 4; j++)    rowB[j] = wn + j * 16 + lr + lc * 8;

    float acc[4][8][4];
    #pragma unroll
    for (int mb = 0; mb < 4; mb++)
        #pragma unroll
        for (int nb = 0; nb < 8; nb++)
            #pragma unroll
            for (int e = 0; e < 4; e++) acc[mb][nb][e] = 0.0f;

    gemm_mainloop(A, B, K, bm, bn, sbase, tid, rowA, rowB, lh, lc, acc);

    #pragma unroll
    for (int mb = 0; mb < 4; mb++) {
        const int r0 = bm + wm + mb * 16 + (lane >> 2);
        #pragma unroll
        for (int nb = 0; nb < 8; nb++) {
            const int gc = bn + wn + nb * 8 + (lane & 3) * 2;
            *(float2*)(C + (size_t)r0 * N + gc) =
                make_float2(acc[mb][nb][0], acc[mb][nb][1]);
            *(float2*)(C + (size_t)(r0 + 8) * N + gc) =
                make_float2(acc[mb][nb][2], acc[mb][nb][3]);
        }
    }
}

// ======================= head-mixing attention =============================
__global__ __launch_bounds__(256)
void attention_kernel(int M) {
    __shared__ float qt[DH * NHEADS];
    __shared__ float kt[DH * NHEADS];
    __shared__ float vs[HID];
    __shared__ float w[NHEADS * NHEADS];

    int p = blockIdx.x;
    int t = threadIdx.x;
    const __half2* qrow = (const __half2*)(g_q16 + (size_t)p * HID);
    const __half2* krow = (const __half2*)(g_k16 + (size_t)p * HID);
    const __half2* vrow = (const __half2*)(g_v16 + (size_t)p * HID);

    for (int c2 = t; c2 < HID / 2; c2 += 256) {
        int c = 2 * c2;
        int n = c / DH;
        int j = c - n * DH;
        float2 qf = __half22float2(qrow[c2]);
        float2 kf = __half22float2(krow[c2]);
        float2 vf = __half22float2(vrow[c2]);
        qt[j * NHEADS + n] = qf.x;
        qt[(j + 1) * NHEADS + n] = qf.y;
        kt[j * NHEADS + n] = kf.x;
        kt[(j + 1) * NHEADS + n] = kf.y;
        vs[c] = vf.x;
        vs[c + 1] = vf.y;
    }
    __syncthreads();

    {
        int m = t >> 4;
        int n = t & 15;
        float acc = 0.0f;
        #pragma unroll 8
        for (int j = 0; j < DH; j++)
            acc += qt[j * NHEADS + n] * kt[j * NHEADS + m];
        w[n * NHEADS + m] = acc * (1.0f / 12.0f);
    }
    __syncthreads();

    if (t < NHEADS) {
        float mx = -1e30f;
        #pragma unroll
        for (int m = 0; m < NHEADS; m++) mx = fmaxf(mx, w[t * NHEADS + m]);
        float sum = 0.0f;
        #pragma unroll
        for (int m = 0; m < NHEADS; m++) {
            float e = expf(w[t * NHEADS + m] - mx);
            w[t * NHEADS + m] = e;
            sum += e;
        }
        float inv = 1.0f / sum;
        #pragma unroll
        for (int m = 0; m < NHEADS; m++) w[t * NHEADS + m] *= inv;
    }
    __syncthreads();

    __half* arow = g_attnh + (size_t)p * HID;
    for (int c = t; c < HID; c += 256) {
        int n = c / DH;
        int j = c - n * DH;
        float acc = 0.0f;
        #pragma unroll
        for (int m = 0; m < NHEADS; m++)
            acc += w[n * NHEADS + m] * vs[m * DH + j];
        arow[c] = __float2half_rn(acc);
    }
}

// ======================= residual + LayerNorm ==============================
__device__ __forceinline__ float block_sum(float v, float* red) {
    #pragma unroll
    for (int o = 16; o > 0; o >>= 1) v += __shfl_xor_sync(0xFFFFFFFFu, v, o);
    int warp = threadIdx.x >> 5, lane = threadIdx.x & 31;
    if (lane == 0) red[warp] = v;
    __syncthreads();
    if (warp == 0) {
        float x = (lane < 8) ? red[lane] : 0.0f;
        #pragma unroll
        for (int o = 4; o > 0; o >>= 1) x += __shfl_xor_sync(0xFFFFFFFFu, x, o);
        if (lane == 0) red[0] = x;
    }
    __syncthreads();
    float r = red[0];
    __syncthreads();
    return r;
}

__global__ __launch_bounds__(256)
void ln_kernel(const float* __restrict__ x, const float* __restrict__ bo,
               const float* __restrict__ gamma, const float* __restrict__ beta,
               float* __restrict__ out) {
    __shared__ float ybuf[HID];
    __shared__ float red[8];

    int row = blockIdx.x;
    int t = threadIdx.x;
    const float* xr = x + (size_t)row * HID;
    const float* orow = g_o + (size_t)row * HID;

    float s = 0.0f;
    for (int c = t; c < HID; c += 256) {
        float y = xr[c] + orow[c] + bo[c];
        ybuf[c] = y;
        s += y;
    }
    float total = block_sum(s, red);
    float mu = total * (1.0f / (float)HID);

    float vsum = 0.0f;
    for (int c = t; c < HID; c += 256) {
        float dy = ybuf[c] - mu;
        vsum += dy * dy;
    }
    float vtot = block_sum(vsum, red);
    float var = vtot * (1.0f / (float)HID);
    float rstd = rsqrtf(var + 1e-5f);

    float* orow_out = out + (size_t)row * HID;
    for (int c = t; c < HID; c += 256) {
        orow_out[c] = (ybuf[c] - mu) * rstd * gamma[c] + beta[c];
    }
}

// ---------------------------------------------------------------------------
extern "C" void kernel_launch(void* const* d_in, const int* in_sizes, int n_in,
                              void* d_out, int out_size) {
    const float* x  = (const float*)d_in[0];
    const float* wq = (const float*)d_in[1];
    const float* bq = (const float*)d_in[2];
    const float* wk = (const float*)d_in[3];
    const float* bk = (const float*)d_in[4];
    const float* wv = (const float*)d_in[5];
    const float* bv = (const float*)d_in[6];
    const float* wo = (const float*)d_in[7];
    const float* bo = (const float*)d_in[8];
    const float* g  = (const float*)d_in[9];
    const float* bl = (const float*)d_in[10];
    float* out = (float*)d_out;

    int M = in_sizes[0] / HID;   // b*s = 8192

    float* o;
    __half *xh, *attnh, *wqkvh, *woh;
    cudaGetSymbolAddress((void**)&o,     g_o);
    cudaGetSymbolAddress((void**)&xh,    g_xh);
    cudaGetSymbolAddress((void**)&attnh, g_attnh);
    cudaGetSymbolAddress((void**)&wqkvh, g_wqkvh);
    cudaGetSymbolAddress((void**)&woh,   g_woh);

    static int smem_set = 0;
    if (!smem_set) {
        cudaFuncSetAttribute(gemm_qkv_kernel,
                             cudaFuncAttributeMaxDynamicSharedMemorySize, GEMM_SMEM_BYTES);
        cudaFuncSetAttribute(gemm_wo_kernel,
                             cudaFuncAttributeMaxDynamicSharedMemorySize, GEMM_SMEM_BYTES);
        smem_set = 1;
    }

    build_omega_kernel<<<(HALF_D + 255) / 256, 256>>>();
    build_rope_kernel<<<(SLEN * HALF_D + 255) / 256, 256>>>();

    // convert inputs to fp16 (RNE); pack q/k/v weights into one buffer
    {
        int nx4 = (M * HID) / 4;
        int nw4 = (HID * HID) / 4;
        to_half_kernel<<<(nx4 + 255) / 256, 256>>>(x,  xh, nx4);
        to_half_kernel<<<(nw4 + 255) / 256, 256>>>(wq, wqkvh,                       nw4);
        to_half_kernel<<<(nw4 + 255) / 256, 256>>>(wk, wqkvh + (size_t)HID * HID,   nw4);
        to_half_kernel<<<(nw4 + 255) / 256, 256>>>(wv, wqkvh + (size_t)2 * HID * HID, nw4);
        to_half_kernel<<<(nw4 + 255) / 256, 256>>>(wo, woh, nw4);
    }

    dim3 qkvgrid(3 * HID / BN, M / BM);   // 54 x 64
    gemm_qkv_kernel<<<qkvgrid, 128, GEMM_SMEM_BYTES>>>(xh, wqkvh, bq, bk, bv, M, HID);

    attention_kernel<<<M, 256>>>(M);

    dim3 wogrid(HID / BN, M / BM);        // 18 x 64
    gemm_wo_kernel<<<wogrid, 128, GEMM_SMEM_BYTES>>>(attnh, woh, o, M, HID, HID);

    ln_kernel<<<M, 256>>>(x, bo, g, bl, out);

    (void)n_in; (void)out_size;
}